// round 1
// baseline (speedup 1.0000x reference)
#include <cuda_runtime.h>
#include <math.h>

#define DIM   512
#define S_LEN 4096
#define NB    4                 // attention batches (2B)
#define ROWS  (NB * S_LEN)      // 16384 rows of D=512

// ---------------- scratch (static device allocations; allowed) ----------------
__device__ float g_norms[ROWS * DIM];
__device__ float g_Q[ROWS * DIM];
__device__ float g_K[ROWS * DIM];
__device__ float g_V[ROWS * DIM];
__device__ float g_X[ROWS * DIM];
__device__ float g_XO[ROWS * DIM];
__device__ float g_S[(size_t)NB * S_LEN * S_LEN];   // 256 MiB scores

// ---------------- LayerNorm over the two input modalities ----------------
// rows 0..2S-1 -> text with (gt,bt); rows 2S..4S-1 -> img with (gi,bi)
__global__ void __launch_bounds__(128) ln_in_kernel(
    const float* __restrict__ text, const float* __restrict__ img,
    const float* __restrict__ gt, const float* __restrict__ bt,
    const float* __restrict__ gi, const float* __restrict__ bi,
    float* __restrict__ out)
{
    int row = blockIdx.x;
    const float *src, *g, *b;
    if (row < 2 * S_LEN) { src = text + (size_t)row * DIM;              g = gt; b = bt; }
    else                 { src = img  + (size_t)(row - 2*S_LEN) * DIM;  g = gi; b = bi; }

    int t = threadIdx.x;                       // 128 threads * 4 = 512
    float4 x = ((const float4*)src)[t];
    float s  = x.x + x.y + x.z + x.w;
    float ss = x.x*x.x + x.y*x.y + x.z*x.z + x.w*x.w;

    __shared__ float rs[4], rss[4];
    #pragma unroll
    for (int o = 16; o > 0; o >>= 1) {
        s  += __shfl_xor_sync(0xffffffffu, s,  o);
        ss += __shfl_xor_sync(0xffffffffu, ss, o);
    }
    if ((t & 31) == 0) { rs[t>>5] = s; rss[t>>5] = ss; }
    __syncthreads();
    s  = rs[0] + rs[1] + rs[2] + rs[3];
    ss = rss[0] + rss[1] + rss[2] + rss[3];

    float mu  = s * (1.0f / DIM);
    float var = ss * (1.0f / DIM) - mu * mu;
    float inv = rsqrtf(var + 1e-5f);

    float4 gg = ((const float4*)g)[t];
    float4 bb = ((const float4*)b)[t];
    float4 o4;
    o4.x = (x.x - mu) * inv * gg.x + bb.x;
    o4.y = (x.y - mu) * inv * gg.y + bb.y;
    o4.z = (x.z - mu) * inv * gg.z + bb.z;
    o4.w = (x.w - mu) * inv * gg.w + bb.w;
    ((float4*)(out + (size_t)row * DIM))[t] = o4;
}

// ---------------- final LayerNorm: 32768 output rows ----------------
// rows 0..16383 -> ln_t(x row r), rows 16384..32767 -> ln_i(x row r-16384)
__global__ void __launch_bounds__(128) ln_out_kernel(
    const float* __restrict__ x,
    const float* __restrict__ gt, const float* __restrict__ bt,
    const float* __restrict__ gi, const float* __restrict__ bi,
    float* __restrict__ out)
{
    int row = blockIdx.x;
    int srow = row & (ROWS - 1);
    const float *g, *b;
    if (row < ROWS) { g = gt; b = bt; } else { g = gi; b = bi; }
    const float* src = x + (size_t)srow * DIM;

    int t = threadIdx.x;
    float4 v = ((const float4*)src)[t];
    float s  = v.x + v.y + v.z + v.w;
    float ss = v.x*v.x + v.y*v.y + v.z*v.z + v.w*v.w;

    __shared__ float rs[4], rss[4];
    #pragma unroll
    for (int o = 16; o > 0; o >>= 1) {
        s  += __shfl_xor_sync(0xffffffffu, s,  o);
        ss += __shfl_xor_sync(0xffffffffu, ss, o);
    }
    if ((t & 31) == 0) { rs[t>>5] = s; rss[t>>5] = ss; }
    __syncthreads();
    s  = rs[0] + rs[1] + rs[2] + rs[3];
    ss = rss[0] + rss[1] + rss[2] + rss[3];

    float mu  = s * (1.0f / DIM);
    float var = ss * (1.0f / DIM) - mu * mu;
    float inv = rsqrtf(var + 1e-5f);

    float4 gg = ((const float4*)g)[t];
    float4 bb = ((const float4*)b)[t];
    float4 o4;
    o4.x = (v.x - mu) * inv * gg.x + bb.x;
    o4.y = (v.y - mu) * inv * gg.y + bb.y;
    o4.z = (v.z - mu) * inv * gg.z + bb.z;
    o4.w = (v.w - mu) * inv * gg.w + bb.w;
    ((float4*)(out + (size_t)row * DIM))[t] = o4;
}

// ---------------- tiled fp32 GEMM: 128x128x8, 8x8 microtile ----------------
// LAYOUT 0 (NT): C = alpha * A[M,K] @ B[N,K]^T + bias   (dot of rows)
// LAYOUT 1 (NN): C = alpha * A[M,K] @ B[K,N]   + bias
template<int LAYOUT>
__global__ void __launch_bounds__(256) gemm_kernel(
    const float* __restrict__ A, const float* __restrict__ B,
    const float* __restrict__ bias, float* __restrict__ C,
    int M, int N, int K, float alpha,
    long long strideA, long long strideB, long long strideC)
{
    __shared__ float As[8][128];
    __shared__ float Bs[8][128];

    int z = blockIdx.z;
    A += (size_t)z * strideA;
    B += (size_t)z * strideB;
    C += (size_t)z * strideC;

    int m0 = blockIdx.y * 128;
    int n0 = blockIdx.x * 128;
    int tid = threadIdx.x;

    // A (and NT-B) loader: 128 rows x 8 cols; one float4 per thread
    int lr = tid >> 1;
    int lc = (tid & 1) * 4;
    // NN-B loader: 8 rows x 128 cols
    int br = tid >> 5;
    int bc = (tid & 31) * 4;

    int tm = (tid >> 4) * 8;
    int tn = (tid & 15) * 8;

    float acc[8][8];
    #pragma unroll
    for (int i = 0; i < 8; i++)
        #pragma unroll
        for (int j = 0; j < 8; j++) acc[i][j] = 0.0f;

    for (int k0 = 0; k0 < K; k0 += 8) {
        float4 a4 = *(const float4*)(A + (size_t)(m0 + lr) * K + k0 + lc);
        As[lc+0][lr] = a4.x; As[lc+1][lr] = a4.y;
        As[lc+2][lr] = a4.z; As[lc+3][lr] = a4.w;

        if (LAYOUT == 0) {
            float4 b4 = *(const float4*)(B + (size_t)(n0 + lr) * K + k0 + lc);
            Bs[lc+0][lr] = b4.x; Bs[lc+1][lr] = b4.y;
            Bs[lc+2][lr] = b4.z; Bs[lc+3][lr] = b4.w;
        } else {
            float4 b4 = *(const float4*)(B + (size_t)(k0 + br) * N + n0 + bc);
            *(float4*)&Bs[br][bc] = b4;
        }
        __syncthreads();

        #pragma unroll
        for (int k = 0; k < 8; k++) {
            float a[8], b[8];
            *(float4*)&a[0] = *(const float4*)&As[k][tm];
            *(float4*)&a[4] = *(const float4*)&As[k][tm + 4];
            *(float4*)&b[0] = *(const float4*)&Bs[k][tn];
            *(float4*)&b[4] = *(const float4*)&Bs[k][tn + 4];
            #pragma unroll
            for (int i = 0; i < 8; i++)
                #pragma unroll
                for (int j = 0; j < 8; j++)
                    acc[i][j] += a[i] * b[j];
        }
        __syncthreads();
    }

    #pragma unroll
    for (int i = 0; i < 8; i++) {
        size_t crow = (size_t)(m0 + tm + i) * N + n0 + tn;
        #pragma unroll
        for (int j = 0; j < 8; j += 4) {
            float4 v;
            float b0 = bias ? bias[n0 + tn + j + 0] : 0.0f;
            float b1 = bias ? bias[n0 + tn + j + 1] : 0.0f;
            float b2 = bias ? bias[n0 + tn + j + 2] : 0.0f;
            float b3 = bias ? bias[n0 + tn + j + 3] : 0.0f;
            v.x = alpha * acc[i][j+0] + b0;
            v.y = alpha * acc[i][j+1] + b1;
            v.z = alpha * acc[i][j+2] + b2;
            v.w = alpha * acc[i][j+3] + b3;
            *(float4*)(C + crow + j) = v;
        }
    }
}

// ---------------- row softmax over S_LEN=4096 ----------------
__global__ void __launch_bounds__(256) softmax_kernel(float* __restrict__ S)
{
    size_t row = blockIdx.x;
    float* p = S + row * S_LEN;
    int t = threadIdx.x;

    float v[16];
    float mx = -1e30f;
    #pragma unroll
    for (int i = 0; i < 16; i++) {
        v[i] = p[t + i * 256];
        mx = fmaxf(mx, v[i]);
    }

    __shared__ float red[8];
    #pragma unroll
    for (int o = 16; o > 0; o >>= 1) mx = fmaxf(mx, __shfl_xor_sync(0xffffffffu, mx, o));
    if ((t & 31) == 0) red[t >> 5] = mx;
    __syncthreads();
    float m = red[0];
    #pragma unroll
    for (int i = 1; i < 8; i++) m = fmaxf(m, red[i]);
    __syncthreads();

    float sum = 0.0f;
    #pragma unroll
    for (int i = 0; i < 16; i++) { v[i] = __expf(v[i] - m); sum += v[i]; }
    #pragma unroll
    for (int o = 16; o > 0; o >>= 1) sum += __shfl_xor_sync(0xffffffffu, sum, o);
    if ((t & 31) == 0) red[t >> 5] = sum;
    __syncthreads();
    float tot = red[0] + red[1] + red[2] + red[3] + red[4] + red[5] + red[6] + red[7];

    float inv = 1.0f / tot;
    #pragma unroll
    for (int i = 0; i < 16; i++) p[t + i * 256] = v[i] * inv;
}

// ---------------- host orchestration ----------------
extern "C" void kernel_launch(void* const* d_in, const int* in_sizes, int n_in,
                              void* d_out, int out_size)
{
    const float* text  = (const float*)d_in[0];
    const float* img   = (const float*)d_in[1];
    const float* ln_tg = (const float*)d_in[2];
    const float* ln_tb = (const float*)d_in[3];
    const float* ln_ig = (const float*)d_in[4];
    const float* ln_ib = (const float*)d_in[5];
    const float* Wq  = (const float*)d_in[6];  const float* bq  = (const float*)d_in[7];
    const float* Wkt = (const float*)d_in[8];  const float* bkt = (const float*)d_in[9];
    const float* Wvt = (const float*)d_in[10]; const float* bvt = (const float*)d_in[11];
    const float* Wki = (const float*)d_in[12]; const float* bki = (const float*)d_in[13];
    const float* Wvi = (const float*)d_in[14]; const float* bvi = (const float*)d_in[15];
    const float* Wo  = (const float*)d_in[16]; const float* bo  = (const float*)d_in[17];
    float* out = (float*)d_out;

    void *p_norms, *p_Q, *p_K, *p_V, *p_X, *p_XO, *p_S;
    cudaGetSymbolAddress(&p_norms, g_norms);
    cudaGetSymbolAddress(&p_Q, g_Q);
    cudaGetSymbolAddress(&p_K, g_K);
    cudaGetSymbolAddress(&p_V, g_V);
    cudaGetSymbolAddress(&p_X, g_X);
    cudaGetSymbolAddress(&p_XO, g_XO);
    cudaGetSymbolAddress(&p_S, g_S);
    float* norms = (float*)p_norms;
    float* Q = (float*)p_Q; float* K = (float*)p_K; float* V = (float*)p_V;
    float* X = (float*)p_X; float* XO = (float*)p_XO; float* S = (float*)p_S;

    const float scale = 0.04419417382415922f;   // 512^-0.5
    const int HALF = 2 * S_LEN;                 // 8192 rows per modality

    // 1) input LayerNorms -> norms [16384, 512]
    ln_in_kernel<<<ROWS, 128>>>(text, img, ln_tg, ln_tb, ln_ig, ln_ib, norms);

    // 2) projections (NT)
    gemm_kernel<0><<<dim3(4, 128, 1), 256>>>(norms, Wq, bq, Q,
        ROWS, DIM, DIM, 1.0f, 0, 0, 0);
    gemm_kernel<0><<<dim3(4, 64, 1), 256>>>(norms, Wkt, bkt, K,
        HALF, DIM, DIM, 1.0f, 0, 0, 0);
    gemm_kernel<0><<<dim3(4, 64, 1), 256>>>(norms + (size_t)HALF * DIM, Wki, bki, K + (size_t)HALF * DIM,
        HALF, DIM, DIM, 1.0f, 0, 0, 0);
    gemm_kernel<0><<<dim3(4, 64, 1), 256>>>(norms, Wvt, bvt, V,
        HALF, DIM, DIM, 1.0f, 0, 0, 0);
    gemm_kernel<0><<<dim3(4, 64, 1), 256>>>(norms + (size_t)HALF * DIM, Wvi, bvi, V + (size_t)HALF * DIM,
        HALF, DIM, DIM, 1.0f, 0, 0, 0);

    // 3) scores = scale * Q @ K^T (batched NT)
    gemm_kernel<0><<<dim3(32, 32, NB), 256>>>(Q, K, nullptr, S,
        S_LEN, S_LEN, DIM, scale,
        (long long)S_LEN * DIM, (long long)S_LEN * DIM, (long long)S_LEN * S_LEN);

    // 4) softmax rows
    softmax_kernel<<<ROWS, 256>>>(S);

    // 5) X = attn @ V (batched NN)
    gemm_kernel<1><<<dim3(4, 32, NB), 256>>>(S, V, nullptr, X,
        S_LEN, DIM, S_LEN, 1.0f,
        (long long)S_LEN * S_LEN, (long long)S_LEN * DIM, (long long)S_LEN * DIM);

    // 6) XO = X @ Wo^T + bo
    gemm_kernel<0><<<dim3(4, 128, 1), 256>>>(X, Wo, bo, XO,
        ROWS, DIM, DIM, 1.0f, 0, 0, 0);

    // 7) final dual LayerNorm -> out [32768, 512]
    ln_out_kernel<<<2 * ROWS, 128>>>(XO, ln_tg, ln_tb, ln_ig, ln_ib, out);
}

// round 4
// speedup vs baseline: 2.8848x; 2.8848x over previous
#include <cuda_runtime.h>
#include <cuda_bf16.h>
#include <cstdint>
#include <math.h>

// ============================================================================
// Problem constants
// ============================================================================
#define DIM   512
#define S_LEN 4096
#define NBAT  4
#define ROWS  (NBAT * S_LEN)      // 16384

// GEMM tiling
#define BM 128
#define BN 128
#define BK 64
#define THREADS 512
#define STAGES 3
#define STAGE_BYTES 65536
#define OFF_AH 0
#define OFF_AL 16384
#define OFF_BH 32768
#define OFF_BL 49152
#define SMEM_DYN (STAGES * STAGE_BYTES)   // 196608

// ============================================================================
// PTX helpers (plain sm_103-legal: cp.async / ldmatrix / mma.sync only)
// ============================================================================
__device__ __forceinline__ uint32_t smem_to_u32(const void* p) {
    uint32_t a;
    asm("{ .reg .u64 t; cvta.to.shared.u64 t, %1; cvt.u32.u64 %0, t; }" : "=r"(a) : "l"(p));
    return a;
}
#define CP_A16(s, g) \
    asm volatile("cp.async.cg.shared.global [%0], [%1], 16;" :: "r"(s), "l"(g))
#define CP_COMMIT() asm volatile("cp.async.commit_group;" ::: "memory")
#define CP_WAIT(n)  asm volatile("cp.async.wait_group %0;" :: "n"(n) : "memory")

__device__ __forceinline__ void ldm_x4(uint32_t* r, uint32_t addr) {
    asm volatile("ldmatrix.sync.aligned.m8n8.x4.shared.b16 {%0,%1,%2,%3}, [%4];"
        : "=r"(r[0]), "=r"(r[1]), "=r"(r[2]), "=r"(r[3]) : "r"(addr));
}
__device__ __forceinline__ void ldm_x4_t(uint32_t* r, uint32_t addr) {
    asm volatile("ldmatrix.sync.aligned.m8n8.x4.trans.shared.b16 {%0,%1,%2,%3}, [%4];"
        : "=r"(r[0]), "=r"(r[1]), "=r"(r[2]), "=r"(r[3]) : "r"(addr));
}
__device__ __forceinline__ void mma_bf16(float* d, const uint32_t* a, const uint32_t* b) {
    asm volatile("mma.sync.aligned.m16n8k16.row.col.f32.bf16.bf16.f32 "
        "{%0,%1,%2,%3}, {%4,%5,%6,%7}, {%8,%9}, {%0,%1,%2,%3};"
        : "+f"(d[0]), "+f"(d[1]), "+f"(d[2]), "+f"(d[3])
        : "r"(a[0]), "r"(a[1]), "r"(a[2]), "r"(a[3]), "r"(b[0]), "r"(b[1]));
}

__device__ __forceinline__ void split_bf16(float v, __nv_bfloat16& h, __nv_bfloat16& l) {
    h = __float2bfloat16(v);
    l = __float2bfloat16(v - __bfloat162float(h));
}

// ============================================================================
// Scratch buffers
// ============================================================================
__device__ __align__(128) __nv_bfloat16 g_normsH[(size_t)ROWS * DIM];
__device__ __align__(128) __nv_bfloat16 g_normsL[(size_t)ROWS * DIM];
__device__ __align__(128) __nv_bfloat16 g_QH[(size_t)ROWS * DIM];
__device__ __align__(128) __nv_bfloat16 g_QL[(size_t)ROWS * DIM];
__device__ __align__(128) __nv_bfloat16 g_KH[(size_t)ROWS * DIM];
__device__ __align__(128) __nv_bfloat16 g_KL[(size_t)ROWS * DIM];
__device__ __align__(128) __nv_bfloat16 g_VH[(size_t)ROWS * DIM];
__device__ __align__(128) __nv_bfloat16 g_VL[(size_t)ROWS * DIM];
__device__ __align__(128) __nv_bfloat16 g_ATH[(size_t)NBAT * S_LEN * S_LEN];
__device__ __align__(128) __nv_bfloat16 g_ATL[(size_t)NBAT * S_LEN * S_LEN];
__device__ __align__(128) __nv_bfloat16 g_XH[(size_t)ROWS * DIM];
__device__ __align__(128) __nv_bfloat16 g_XL[(size_t)ROWS * DIM];
__device__ __align__(128) __nv_bfloat16 g_WH[(size_t)6 * DIM * DIM];
__device__ __align__(128) __nv_bfloat16 g_WL[(size_t)6 * DIM * DIM];
__device__ __align__(128) float g_S[(size_t)NBAT * S_LEN * S_LEN];
__device__ __align__(128) float g_XO[(size_t)ROWS * DIM];

// ============================================================================
// Input LayerNorm -> split bf16 norms
// ============================================================================
__global__ void __launch_bounds__(128) ln_in_split_kernel(
    const float* __restrict__ text, const float* __restrict__ img,
    const float* __restrict__ gt, const float* __restrict__ bt,
    const float* __restrict__ gi, const float* __restrict__ bi,
    __nv_bfloat16* __restrict__ outH, __nv_bfloat16* __restrict__ outL)
{
    int row = blockIdx.x;
    const float *src, *g, *b;
    if (row < 2 * S_LEN) { src = text + (size_t)row * DIM;              g = gt; b = bt; }
    else                 { src = img  + (size_t)(row - 2*S_LEN) * DIM;  g = gi; b = bi; }

    int t = threadIdx.x;
    float4 x = ((const float4*)src)[t];
    float s  = x.x + x.y + x.z + x.w;
    float ss = x.x*x.x + x.y*x.y + x.z*x.z + x.w*x.w;

    __shared__ float rs[4], rss[4];
    #pragma unroll
    for (int o = 16; o > 0; o >>= 1) {
        s  += __shfl_xor_sync(0xffffffffu, s,  o);
        ss += __shfl_xor_sync(0xffffffffu, ss, o);
    }
    if ((t & 31) == 0) { rs[t>>5] = s; rss[t>>5] = ss; }
    __syncthreads();
    s  = rs[0] + rs[1] + rs[2] + rs[3];
    ss = rss[0] + rss[1] + rss[2] + rss[3];

    float mu  = s * (1.0f / DIM);
    float var = ss * (1.0f / DIM) - mu * mu;
    float inv = rsqrtf(var + 1e-5f);

    float4 gg = ((const float4*)g)[t];
    float4 bb = ((const float4*)b)[t];
    float v0 = (x.x - mu) * inv * gg.x + bb.x;
    float v1 = (x.y - mu) * inv * gg.y + bb.y;
    float v2 = (x.z - mu) * inv * gg.z + bb.z;
    float v3 = (x.w - mu) * inv * gg.w + bb.w;

    size_t base = (size_t)row * DIM + t * 4;
    __nv_bfloat16 h0,h1,h2,h3,l0,l1,l2,l3;
    split_bf16(v0,h0,l0); split_bf16(v1,h1,l1); split_bf16(v2,h2,l2); split_bf16(v3,h3,l3);
    ((__nv_bfloat162*)(outH + base))[0] = __nv_bfloat162(h0, h1);
    ((__nv_bfloat162*)(outH + base))[1] = __nv_bfloat162(h2, h3);
    ((__nv_bfloat162*)(outL + base))[0] = __nv_bfloat162(l0, l1);
    ((__nv_bfloat162*)(outL + base))[1] = __nv_bfloat162(l2, l3);
}

// ============================================================================
// Split 6 weight matrices into hi/lo bf16
// ============================================================================
__global__ void __launch_bounds__(256) split_weights_kernel(
    const float* __restrict__ w0, const float* __restrict__ w1,
    const float* __restrict__ w2, const float* __restrict__ w3,
    const float* __restrict__ w4, const float* __restrict__ w5,
    __nv_bfloat16* __restrict__ WH, __nv_bfloat16* __restrict__ WL)
{
    int mat = blockIdx.y;
    const float* ws[6] = {w0, w1, w2, w3, w4, w5};
    const float* w = ws[mat];
    int i = blockIdx.x * 256 + threadIdx.x;
    float v = w[i];
    __nv_bfloat16 h, l;
    split_bf16(v, h, l);
    size_t o = (size_t)mat * DIM * DIM + i;
    WH[o] = h; WL[o] = l;
}

// ============================================================================
// Softmax rows of S (fp32) -> split bf16 attention weights
// ============================================================================
__global__ void __launch_bounds__(256) softmax_split_kernel(
    const float* __restrict__ S, __nv_bfloat16* __restrict__ AH, __nv_bfloat16* __restrict__ AL)
{
    size_t row = blockIdx.x;
    const float* p = S + row * S_LEN;
    int t = threadIdx.x;

    float v[16];
    float mx = -1e30f;
    #pragma unroll
    for (int i = 0; i < 16; i++) { v[i] = p[t + i * 256]; mx = fmaxf(mx, v[i]); }

    __shared__ float red[8];
    #pragma unroll
    for (int o = 16; o > 0; o >>= 1) mx = fmaxf(mx, __shfl_xor_sync(0xffffffffu, mx, o));
    if ((t & 31) == 0) red[t >> 5] = mx;
    __syncthreads();
    float m = red[0];
    #pragma unroll
    for (int i = 1; i < 8; i++) m = fmaxf(m, red[i]);
    __syncthreads();

    float sum = 0.0f;
    #pragma unroll
    for (int i = 0; i < 16; i++) { v[i] = __expf(v[i] - m); sum += v[i]; }
    #pragma unroll
    for (int o = 16; o > 0; o >>= 1) sum += __shfl_xor_sync(0xffffffffu, sum, o);
    if ((t & 31) == 0) red[t >> 5] = sum;
    __syncthreads();
    float tot = red[0] + red[1] + red[2] + red[3] + red[4] + red[5] + red[6] + red[7];

    float inv = 1.0f / tot;
    size_t base = row * S_LEN;
    #pragma unroll
    for (int i = 0; i < 16; i++) {
        float pv = v[i] * inv;
        __nv_bfloat16 h, l;
        split_bf16(pv, h, l);
        AH[base + t + i * 256] = h;
        AL[base + t + i * 256] = l;
    }
}

// ============================================================================
// Final dual LayerNorm (fp32 in/out)
// ============================================================================
__global__ void __launch_bounds__(128) ln_out_kernel(
    const float* __restrict__ x,
    const float* __restrict__ gt, const float* __restrict__ bt,
    const float* __restrict__ gi, const float* __restrict__ bi,
    float* __restrict__ out)
{
    int row = blockIdx.x;
    int srow = row & (ROWS - 1);
    const float *g, *b;
    if (row < ROWS) { g = gt; b = bt; } else { g = gi; b = bi; }
    const float* src = x + (size_t)srow * DIM;

    int t = threadIdx.x;
    float4 v = ((const float4*)src)[t];
    float s  = v.x + v.y + v.z + v.w;
    float ss = v.x*v.x + v.y*v.y + v.z*v.z + v.w*v.w;

    __shared__ float rs[4], rss[4];
    #pragma unroll
    for (int o = 16; o > 0; o >>= 1) {
        s  += __shfl_xor_sync(0xffffffffu, s,  o);
        ss += __shfl_xor_sync(0xffffffffu, ss, o);
    }
    if ((t & 31) == 0) { rs[t>>5] = s; rss[t>>5] = ss; }
    __syncthreads();
    s  = rs[0] + rs[1] + rs[2] + rs[3];
    ss = rss[0] + rss[1] + rss[2] + rss[3];

    float mu  = s * (1.0f / DIM);
    float var = ss * (1.0f / DIM) - mu * mu;
    float inv = rsqrtf(var + 1e-5f);

    float4 gg = ((const float4*)g)[t];
    float4 bb = ((const float4*)b)[t];
    float4 o4;
    o4.x = (v.x - mu) * inv * gg.x + bb.x;
    o4.y = (v.y - mu) * inv * gg.y + bb.y;
    o4.z = (v.z - mu) * inv * gg.z + bb.z;
    o4.w = (v.w - mu) * inv * gg.w + bb.w;
    ((float4*)(out + (size_t)row * DIM))[t] = o4;
}

// ============================================================================
// mma.sync bf16 split-precision GEMM.
//   C[M,N] = alpha * (A_hi+A_lo)[M,K] @ B (+ bias)
// LAYOUT 0 (NT): B = [N,K] k-contiguous (dot of rows)
// LAYOUT 1 (NN): B = [K,N] n-contiguous (ldmatrix.trans)
// EPI 0: fp32 C (alpha + optional bias)
// EPI 1: split bf16 CH/CL (alpha + optional bias)
// 3 MMA passes per tile: AhBh + AhBl + AlBh, fp32 accumulate.
// ============================================================================
template<int LAYOUT, int EPI>
__global__ void __launch_bounds__(THREADS, 1) mma_gemm_kernel(
    const __nv_bfloat16* __restrict__ AH, const __nv_bfloat16* __restrict__ AL,
    const __nv_bfloat16* __restrict__ BH, const __nv_bfloat16* __restrict__ BL,
    const float* __restrict__ bias,
    float* __restrict__ Cf, __nv_bfloat16* __restrict__ CH, __nv_bfloat16* __restrict__ CL,
    int M, int N, int K, float alpha,
    long long sA, long long sB, long long sC)
{
    extern __shared__ char smem[];
    uint32_t base = smem_to_u32(smem);
    int tid = threadIdx.x, wid = tid >> 5, lane = tid & 31;

    int z = blockIdx.z;
    AH += (size_t)z * sA; AL += (size_t)z * sA;
    BH += (size_t)z * sB; BL += (size_t)z * sB;

    int m0 = blockIdx.y * BM;
    int n0 = blockIdx.x * BN;
    int NK = K / BK;

    auto load_stage = [&](int kt) {
        uint32_t sb = base + (uint32_t)(kt % STAGES) * STAGE_BYTES;
        int kb = kt * BK;
        // A: 128 rows x 128B (hi & lo), SW128 swizzle
        #pragma unroll
        for (int i = 0; i < 2; i++) {
            int slot = tid + i * THREADS;
            int row = slot >> 3, unit = slot & 7;
            const __nv_bfloat16* gH = AH + (size_t)(m0 + row) * K + kb + unit * 8;
            const __nv_bfloat16* gL = AL + (size_t)(m0 + row) * K + kb + unit * 8;
            uint32_t off = (uint32_t)(row * 128 + unit * 16);
            off ^= (off >> 3) & 0x70;
            CP_A16(sb + OFF_AH + off, gH);
            CP_A16(sb + OFF_AL + off, gL);
        }
        if (LAYOUT == 0) {
            // B NT: 128 rows x 128B
            #pragma unroll
            for (int i = 0; i < 2; i++) {
                int slot = tid + i * THREADS;
                int row = slot >> 3, unit = slot & 7;
                const __nv_bfloat16* gH = BH + (size_t)(n0 + row) * K + kb + unit * 8;
                const __nv_bfloat16* gL = BL + (size_t)(n0 + row) * K + kb + unit * 8;
                uint32_t off = (uint32_t)(row * 128 + unit * 16);
                off ^= (off >> 3) & 0x70;
                CP_A16(sb + OFF_BH + off, gH);
                CP_A16(sb + OFF_BL + off, gL);
            }
        } else {
            // B NN: 64 k-rows x 256B (BN=128 bf16)
            #pragma unroll
            for (int i = 0; i < 2; i++) {
                int slot = tid + i * THREADS;
                int row = slot >> 4, unit = slot & 15;
                const __nv_bfloat16* gH = BH + (size_t)(kb + row) * N + n0 + unit * 8;
                const __nv_bfloat16* gL = BL + (size_t)(kb + row) * N + n0 + unit * 8;
                uint32_t off = (uint32_t)(row * 256 + unit * 16);
                off ^= (off >> 4) & 0x70;
                CP_A16(sb + OFF_BH + off, gH);
                CP_A16(sb + OFF_BL + off, gL);
            }
        }
    };

    load_stage(0); CP_COMMIT();
    load_stage(1); CP_COMMIT();

    int wm = wid & 3, wn = wid >> 2;     // 4x4 warp grid, 32x32 warp tile
    float acc[2][4][4];
    #pragma unroll
    for (int a = 0; a < 2; a++)
        #pragma unroll
        for (int b = 0; b < 4; b++)
            #pragma unroll
            for (int c = 0; c < 4; c++) acc[a][b][c] = 0.0f;

    for (int kt = 0; kt < NK; kt++) {
        if (kt + 2 < NK)      { load_stage(kt + 2); CP_COMMIT(); CP_WAIT(2); }
        else if (kt + 1 < NK) { CP_WAIT(1); }
        else                  { CP_WAIT(0); }
        __syncthreads();

        uint32_t sb = base + (uint32_t)(kt % STAGES) * STAGE_BYTES;

        #pragma unroll
        for (int ks = 0; ks < 4; ks++) {
            int k0 = ks * 16;

            uint32_t ah[2][4], al[2][4];
            #pragma unroll
            for (int mt = 0; mt < 2; mt++) {
                int row = wm * 32 + mt * 16 + (lane & 15);
                uint32_t off = (uint32_t)(row * 128 + k0 * 2 + ((lane >> 4) << 4));
                off ^= (off >> 3) & 0x70;
                ldm_x4(ah[mt], sb + OFF_AH + off);
                ldm_x4(al[mt], sb + OFF_AL + off);
            }

            uint32_t bh[4][2], bl[4][2];
            if (LAYOUT == 0) {
                #pragma unroll
                for (int p = 0; p < 2; p++) {
                    int nrow = wn * 32 + p * 16 + (lane & 7) + 8 * ((lane >> 4) & 1);
                    uint32_t off = (uint32_t)(nrow * 128 + k0 * 2 + ((lane >> 3) & 1) * 16);
                    off ^= (off >> 3) & 0x70;
                    uint32_t r[4];
                    ldm_x4(r, sb + OFF_BH + off);
                    bh[p*2][0] = r[0]; bh[p*2][1] = r[1];
                    bh[p*2+1][0] = r[2]; bh[p*2+1][1] = r[3];
                    ldm_x4(r, sb + OFF_BL + off);
                    bl[p*2][0] = r[0]; bl[p*2][1] = r[1];
                    bl[p*2+1][0] = r[2]; bl[p*2+1][1] = r[3];
                }
            } else {
                #pragma unroll
                for (int p = 0; p < 2; p++) {
                    int krow = k0 + (lane & 7) + 8 * ((lane >> 3) & 1);
                    int ncol = wn * 32 + p * 16 + 8 * (lane >> 4);
                    uint32_t off = (uint32_t)(krow * 256 + ncol * 2);
                    off ^= (off >> 4) & 0x70;
                    uint32_t r[4];
                    ldm_x4_t(r, sb + OFF_BH + off);
                    bh[p*2][0] = r[0]; bh[p*2][1] = r[1];
                    bh[p*2+1][0] = r[2]; bh[p*2+1][1] = r[3];
                    ldm_x4_t(r, sb + OFF_BL + off);
                    bl[p*2][0] = r[0]; bl[p*2][1] = r[1];
                    bl[p*2+1][0] = r[2]; bl[p*2+1][1] = r[3];
                }
            }

            #pragma unroll
            for (int mt = 0; mt < 2; mt++)
                #pragma unroll
                for (int nt = 0; nt < 4; nt++) {
                    mma_bf16(acc[mt][nt], ah[mt], bh[nt]);
                    mma_bf16(acc[mt][nt], ah[mt], bl[nt]);
                    mma_bf16(acc[mt][nt], al[mt], bh[nt]);
                }
        }
        __syncthreads();
    }

    // ---------------- epilogue ----------------
    #pragma unroll
    for (int mt = 0; mt < 2; mt++) {
        #pragma unroll
        for (int nt = 0; nt < 4; nt++) {
            int m = m0 + wm * 32 + mt * 16 + (lane >> 2);
            int n = n0 + wn * 32 + nt * 8 + (lane & 3) * 2;
            float b0 = bias ? __ldg(&bias[n])     : 0.0f;
            float b1 = bias ? __ldg(&bias[n + 1]) : 0.0f;
            float c0 = alpha * acc[mt][nt][0] + b0;
            float c1 = alpha * acc[mt][nt][1] + b1;
            float c2 = alpha * acc[mt][nt][2] + b0;
            float c3 = alpha * acc[mt][nt][3] + b1;
            if (EPI == 0) {
                float2* p0 = (float2*)(Cf + (size_t)z * sC + (size_t)m * N + n);
                float2* p1 = (float2*)(Cf + (size_t)z * sC + (size_t)(m + 8) * N + n);
                *p0 = make_float2(c0, c1);
                *p1 = make_float2(c2, c3);
            } else {
                __nv_bfloat16 h0,l0,h1,l1,h2,l2,h3,l3;
                split_bf16(c0,h0,l0); split_bf16(c1,h1,l1);
                split_bf16(c2,h2,l2); split_bf16(c3,h3,l3);
                size_t o0 = (size_t)z * sC + (size_t)m * N + n;
                size_t o1 = (size_t)z * sC + (size_t)(m + 8) * N + n;
                *(__nv_bfloat162*)(CH + o0) = __nv_bfloat162(h0, h1);
                *(__nv_bfloat162*)(CL + o0) = __nv_bfloat162(l0, l1);
                *(__nv_bfloat162*)(CH + o1) = __nv_bfloat162(h2, h3);
                *(__nv_bfloat162*)(CL + o1) = __nv_bfloat162(l2, l3);
            }
        }
    }
}

// ============================================================================
// Host orchestration
// ============================================================================
extern "C" void kernel_launch(void* const* d_in, const int* in_sizes, int n_in,
                              void* d_out, int out_size)
{
    const float* text  = (const float*)d_in[0];
    const float* img   = (const float*)d_in[1];
    const float* ln_tg = (const float*)d_in[2];
    const float* ln_tb = (const float*)d_in[3];
    const float* ln_ig = (const float*)d_in[4];
    const float* ln_ib = (const float*)d_in[5];
    const float* Wq  = (const float*)d_in[6];  const float* bq  = (const float*)d_in[7];
    const float* Wkt = (const float*)d_in[8];  const float* bkt = (const float*)d_in[9];
    const float* Wvt = (const float*)d_in[10]; const float* bvt = (const float*)d_in[11];
    const float* Wki = (const float*)d_in[12]; const float* bki = (const float*)d_in[13];
    const float* Wvi = (const float*)d_in[14]; const float* bvi = (const float*)d_in[15];
    const float* Wo  = (const float*)d_in[16]; const float* bo  = (const float*)d_in[17];
    float* out = (float*)d_out;

    static bool attr_done = false;
    if (!attr_done) {
        cudaFuncSetAttribute(mma_gemm_kernel<0,0>, cudaFuncAttributeMaxDynamicSharedMemorySize, SMEM_DYN);
        cudaFuncSetAttribute(mma_gemm_kernel<0,1>, cudaFuncAttributeMaxDynamicSharedMemorySize, SMEM_DYN);
        cudaFuncSetAttribute(mma_gemm_kernel<1,1>, cudaFuncAttributeMaxDynamicSharedMemorySize, SMEM_DYN);
        attr_done = true;
    }

    void *pNH, *pNL, *pQH, *pQL, *pKH, *pKL, *pVH, *pVL, *pATH, *pATL, *pXH, *pXL, *pWH, *pWL, *pS, *pXO;
    cudaGetSymbolAddress(&pNH, g_normsH); cudaGetSymbolAddress(&pNL, g_normsL);
    cudaGetSymbolAddress(&pQH, g_QH);     cudaGetSymbolAddress(&pQL, g_QL);
    cudaGetSymbolAddress(&pKH, g_KH);     cudaGetSymbolAddress(&pKL, g_KL);
    cudaGetSymbolAddress(&pVH, g_VH);     cudaGetSymbolAddress(&pVL, g_VL);
    cudaGetSymbolAddress(&pATH, g_ATH);   cudaGetSymbolAddress(&pATL, g_ATL);
    cudaGetSymbolAddress(&pXH, g_XH);     cudaGetSymbolAddress(&pXL, g_XL);
    cudaGetSymbolAddress(&pWH, g_WH);     cudaGetSymbolAddress(&pWL, g_WL);
    cudaGetSymbolAddress(&pS, g_S);       cudaGetSymbolAddress(&pXO, g_XO);

    __nv_bfloat16* NH = (__nv_bfloat16*)pNH;   __nv_bfloat16* NL = (__nv_bfloat16*)pNL;
    __nv_bfloat16* QH = (__nv_bfloat16*)pQH;   __nv_bfloat16* QL = (__nv_bfloat16*)pQL;
    __nv_bfloat16* KH = (__nv_bfloat16*)pKH;   __nv_bfloat16* KL = (__nv_bfloat16*)pKL;
    __nv_bfloat16* VH = (__nv_bfloat16*)pVH;   __nv_bfloat16* VL = (__nv_bfloat16*)pVL;
    __nv_bfloat16* ATH = (__nv_bfloat16*)pATH; __nv_bfloat16* ATL = (__nv_bfloat16*)pATL;
    __nv_bfloat16* XH = (__nv_bfloat16*)pXH;   __nv_bfloat16* XL = (__nv_bfloat16*)pXL;
    __nv_bfloat16* WH = (__nv_bfloat16*)pWH;   __nv_bfloat16* WL = (__nv_bfloat16*)pWL;
    float* S  = (float*)pS;
    float* XO = (float*)pXO;

    const float scale = 0.04419417382415922f;  // 512^-0.5
    const int HALF = 2 * S_LEN;                // 8192 rows per modality
    const size_t WSZ = (size_t)DIM * DIM;      // 262144

    // 1) input LN + split
    ln_in_split_kernel<<<ROWS, 128>>>(text, img, ln_tg, ln_tb, ln_ig, ln_ib, NH, NL);

    // 2) split weights (order: q, kt, vt, ki, vi, o)
    split_weights_kernel<<<dim3(1024, 6), 256>>>(Wq, Wkt, Wvt, Wki, Wvi, Wo, WH, WL);

    // 3) projections (NT, split bf16 out)
    mma_gemm_kernel<0,1><<<dim3(4, 128, 1), THREADS, SMEM_DYN>>>(
        NH, NL, WH + 0*WSZ, WL + 0*WSZ, bq, nullptr, QH, QL,
        ROWS, DIM, DIM, 1.0f, 0, 0, 0);
    mma_gemm_kernel<0,1><<<dim3(4, 64, 1), THREADS, SMEM_DYN>>>(
        NH, NL, WH + 1*WSZ, WL + 1*WSZ, bkt, nullptr, KH, KL,
        HALF, DIM, DIM, 1.0f, 0, 0, 0);
    mma_gemm_kernel<0,1><<<dim3(4, 64, 1), THREADS, SMEM_DYN>>>(
        NH + (size_t)HALF * DIM, NL + (size_t)HALF * DIM,
        WH + 3*WSZ, WL + 3*WSZ, bki, nullptr,
        KH + (size_t)HALF * DIM, KL + (size_t)HALF * DIM,
        HALF, DIM, DIM, 1.0f, 0, 0, 0);
    mma_gemm_kernel<0,1><<<dim3(4, 64, 1), THREADS, SMEM_DYN>>>(
        NH, NL, WH + 2*WSZ, WL + 2*WSZ, bvt, nullptr, VH, VL,
        HALF, DIM, DIM, 1.0f, 0, 0, 0);
    mma_gemm_kernel<0,1><<<dim3(4, 64, 1), THREADS, SMEM_DYN>>>(
        NH + (size_t)HALF * DIM, NL + (size_t)HALF * DIM,
        WH + 4*WSZ, WL + 4*WSZ, bvi, nullptr,
        VH + (size_t)HALF * DIM, VL + (size_t)HALF * DIM,
        HALF, DIM, DIM, 1.0f, 0, 0, 0);

    // 4) scores = scale * Q @ K^T (batched NT, fp32 out)
    mma_gemm_kernel<0,0><<<dim3(32, 32, NBAT), THREADS, SMEM_DYN>>>(
        QH, QL, KH, KL, nullptr, S, nullptr, nullptr,
        S_LEN, S_LEN, DIM, scale,
        (long long)S_LEN * DIM, (long long)S_LEN * DIM, (long long)S_LEN * S_LEN);

    // 5) softmax + split
    softmax_split_kernel<<<ROWS, 256>>>(S, ATH, ATL);

    // 6) X = attn @ V (batched NN: V natural [seq][dim] layout, split bf16 out)
    mma_gemm_kernel<1,1><<<dim3(4, 32, NBAT), THREADS, SMEM_DYN>>>(
        ATH, ATL, VH, VL, nullptr, nullptr, XH, XL,
        S_LEN, DIM, S_LEN, 1.0f,
        (long long)S_LEN * S_LEN, (long long)S_LEN * DIM, (long long)S_LEN * DIM);

    // 7) XO = X @ Wo^T + bo (NT, fp32 out)
    mma_gemm_kernel<0,0><<<dim3(4, 128, 1), THREADS, SMEM_DYN>>>(
        XH, XL, WH + 5*WSZ, WL + 5*WSZ, bo, XO, nullptr, nullptr,
        ROWS, DIM, DIM, 1.0f, 0, 0, 0);

    // 8) final dual LayerNorm
    ln_out_kernel<<<2 * ROWS, 128>>>(XO, ln_tg, ln_tb, ln_ig, ln_ib, out);
}

// round 6
// speedup vs baseline: 3.1295x; 1.0848x over previous
#include <cuda_runtime.h>
#include <cuda_bf16.h>
#include <cstdint>
#include <math.h>

// ============================================================================
// Problem constants
// ============================================================================
#define DIM   512
#define S_LEN 4096
#define NBAT  4
#define ROWS  (NBAT * S_LEN)      // 16384

// GEMM tiling: BM=128, BN=64, BK=32, 256 threads (8 warps, 4x2 grid, 32x32 warp tile)
#define BM 128
#define BN 64
#define BK 32
#define THREADS 256
#define STAGES 4
// stage layout: AH 8KB | AL 8KB | BH 4KB | BL 4KB = 24KB
#define OFF_AH 0
#define OFF_AL 8192
#define OFF_BH 16384
#define OFF_BL 20480
#define STAGE_BYTES 24576
#define SMEM_DYN (STAGES * STAGE_BYTES)   // 98304

// ============================================================================
// PTX helpers (plain sm_103-legal: cp.async / ldmatrix / mma.sync only)
// ============================================================================
__device__ __forceinline__ uint32_t smem_to_u32(const void* p) {
    uint32_t a;
    asm("{ .reg .u64 t; cvta.to.shared.u64 t, %1; cvt.u32.u64 %0, t; }" : "=r"(a) : "l"(p));
    return a;
}
#define CP_A16(s, g) \
    asm volatile("cp.async.cg.shared.global [%0], [%1], 16;" :: "r"(s), "l"(g))
#define CP_COMMIT() asm volatile("cp.async.commit_group;" ::: "memory")
#define CP_WAIT(n)  asm volatile("cp.async.wait_group %0;" :: "n"(n) : "memory")

__device__ __forceinline__ void ldm_x4(uint32_t* r, uint32_t addr) {
    asm volatile("ldmatrix.sync.aligned.m8n8.x4.shared.b16 {%0,%1,%2,%3}, [%4];"
        : "=r"(r[0]), "=r"(r[1]), "=r"(r[2]), "=r"(r[3]) : "r"(addr));
}
__device__ __forceinline__ void ldm_x4_t(uint32_t* r, uint32_t addr) {
    asm volatile("ldmatrix.sync.aligned.m8n8.x4.trans.shared.b16 {%0,%1,%2,%3}, [%4];"
        : "=r"(r[0]), "=r"(r[1]), "=r"(r[2]), "=r"(r[3]) : "r"(addr));
}
__device__ __forceinline__ void mma_bf16(float* d, const uint32_t* a, const uint32_t* b) {
    asm volatile("mma.sync.aligned.m16n8k16.row.col.f32.bf16.bf16.f32 "
        "{%0,%1,%2,%3}, {%4,%5,%6,%7}, {%8,%9}, {%0,%1,%2,%3};"
        : "+f"(d[0]), "+f"(d[1]), "+f"(d[2]), "+f"(d[3])
        : "r"(a[0]), "r"(a[1]), "r"(a[2]), "r"(a[3]), "r"(b[0]), "r"(b[1]));
}

__device__ __forceinline__ void split_bf16(float v, __nv_bfloat16& h, __nv_bfloat16& l) {
    h = __float2bfloat16(v);
    l = __float2bfloat16(v - __bfloat162float(h));
}

// ============================================================================
// Scratch buffers
// ============================================================================
__device__ __align__(128) __nv_bfloat16 g_normsH[(size_t)ROWS * DIM];
__device__ __align__(128) __nv_bfloat16 g_normsL[(size_t)ROWS * DIM];
__device__ __align__(128) __nv_bfloat16 g_QH[(size_t)ROWS * DIM];
__device__ __align__(128) __nv_bfloat16 g_QL[(size_t)ROWS * DIM];
__device__ __align__(128) __nv_bfloat16 g_KH[(size_t)ROWS * DIM];
__device__ __align__(128) __nv_bfloat16 g_KL[(size_t)ROWS * DIM];
__device__ __align__(128) __nv_bfloat16 g_VH[(size_t)ROWS * DIM];
__device__ __align__(128) __nv_bfloat16 g_VL[(size_t)ROWS * DIM];
__device__ __align__(128) __nv_bfloat16 g_ATH[(size_t)NBAT * S_LEN * S_LEN];
__device__ __align__(128) __nv_bfloat16 g_ATL[(size_t)NBAT * S_LEN * S_LEN];
__device__ __align__(128) __nv_bfloat16 g_XH[(size_t)ROWS * DIM];
__device__ __align__(128) __nv_bfloat16 g_XL[(size_t)ROWS * DIM];
__device__ __align__(128) __nv_bfloat16 g_WH[(size_t)6 * DIM * DIM];
__device__ __align__(128) __nv_bfloat16 g_WL[(size_t)6 * DIM * DIM];
__device__ __align__(128) float g_S[(size_t)NBAT * S_LEN * S_LEN];
__device__ __align__(128) float g_XO[(size_t)ROWS * DIM];

// ============================================================================
// Input LayerNorm -> split bf16 norms
// ============================================================================
__global__ void __launch_bounds__(128) ln_in_split_kernel(
    const float* __restrict__ text, const float* __restrict__ img,
    const float* __restrict__ gt, const float* __restrict__ bt,
    const float* __restrict__ gi, const float* __restrict__ bi,
    __nv_bfloat16* __restrict__ outH, __nv_bfloat16* __restrict__ outL)
{
    int row = blockIdx.x;
    const float *src, *g, *b;
    if (row < 2 * S_LEN) { src = text + (size_t)row * DIM;              g = gt; b = bt; }
    else                 { src = img  + (size_t)(row - 2*S_LEN) * DIM;  g = gi; b = bi; }

    int t = threadIdx.x;
    float4 x = ((const float4*)src)[t];
    float s  = x.x + x.y + x.z + x.w;
    float ss = x.x*x.x + x.y*x.y + x.z*x.z + x.w*x.w;

    __shared__ float rs[4], rss[4];
    #pragma unroll
    for (int o = 16; o > 0; o >>= 1) {
        s  += __shfl_xor_sync(0xffffffffu, s,  o);
        ss += __shfl_xor_sync(0xffffffffu, ss, o);
    }
    if ((t & 31) == 0) { rs[t>>5] = s; rss[t>>5] = ss; }
    __syncthreads();
    s  = rs[0] + rs[1] + rs[2] + rs[3];
    ss = rss[0] + rss[1] + rss[2] + rss[3];

    float mu  = s * (1.0f / DIM);
    float var = ss * (1.0f / DIM) - mu * mu;
    float inv = rsqrtf(var + 1e-5f);

    float4 gg = ((const float4*)g)[t];
    float4 bb = ((const float4*)b)[t];
    float v0 = (x.x - mu) * inv * gg.x + bb.x;
    float v1 = (x.y - mu) * inv * gg.y + bb.y;
    float v2 = (x.z - mu) * inv * gg.z + bb.z;
    float v3 = (x.w - mu) * inv * gg.w + bb.w;

    size_t base = (size_t)row * DIM + t * 4;
    __nv_bfloat16 h0,h1,h2,h3,l0,l1,l2,l3;
    split_bf16(v0,h0,l0); split_bf16(v1,h1,l1); split_bf16(v2,h2,l2); split_bf16(v3,h3,l3);
    ((__nv_bfloat162*)(outH + base))[0] = __nv_bfloat162(h0, h1);
    ((__nv_bfloat162*)(outH + base))[1] = __nv_bfloat162(h2, h3);
    ((__nv_bfloat162*)(outL + base))[0] = __nv_bfloat162(l0, l1);
    ((__nv_bfloat162*)(outL + base))[1] = __nv_bfloat162(l2, l3);
}

// ============================================================================
// Split 6 weight matrices into hi/lo bf16
// ============================================================================
__global__ void __launch_bounds__(256) split_weights_kernel(
    const float* __restrict__ w0, const float* __restrict__ w1,
    const float* __restrict__ w2, const float* __restrict__ w3,
    const float* __restrict__ w4, const float* __restrict__ w5,
    __nv_bfloat16* __restrict__ WH, __nv_bfloat16* __restrict__ WL)
{
    int mat = blockIdx.y;
    const float* ws[6] = {w0, w1, w2, w3, w4, w5};
    const float* w = ws[mat];
    int i = blockIdx.x * 256 + threadIdx.x;
    float v = w[i];
    __nv_bfloat16 h, l;
    split_bf16(v, h, l);
    size_t o = (size_t)mat * DIM * DIM + i;
    WH[o] = h; WL[o] = l;
}

// ============================================================================
// Softmax rows of S (fp32) -> split bf16 attention weights
// ============================================================================
__global__ void __launch_bounds__(256) softmax_split_kernel(
    const float* __restrict__ S, __nv_bfloat16* __restrict__ AH, __nv_bfloat16* __restrict__ AL)
{
    size_t row = blockIdx.x;
    const float* p = S + row * S_LEN;
    int t = threadIdx.x;

    float v[16];
    float mx = -1e30f;
    #pragma unroll
    for (int i = 0; i < 16; i++) { v[i] = p[t + i * 256]; mx = fmaxf(mx, v[i]); }

    __shared__ float red[8];
    #pragma unroll
    for (int o = 16; o > 0; o >>= 1) mx = fmaxf(mx, __shfl_xor_sync(0xffffffffu, mx, o));
    if ((t & 31) == 0) red[t >> 5] = mx;
    __syncthreads();
    float m = red[0];
    #pragma unroll
    for (int i = 1; i < 8; i++) m = fmaxf(m, red[i]);
    __syncthreads();

    float sum = 0.0f;
    #pragma unroll
    for (int i = 0; i < 16; i++) { v[i] = __expf(v[i] - m); sum += v[i]; }
    #pragma unroll
    for (int o = 16; o > 0; o >>= 1) sum += __shfl_xor_sync(0xffffffffu, sum, o);
    if ((t & 31) == 0) red[t >> 5] = sum;
    __syncthreads();
    float tot = red[0] + red[1] + red[2] + red[3] + red[4] + red[5] + red[6] + red[7];

    float inv = 1.0f / tot;
    size_t base = row * S_LEN;
    #pragma unroll
    for (int i = 0; i < 16; i++) {
        float pv = v[i] * inv;
        __nv_bfloat16 h, l;
        split_bf16(pv, h, l);
        AH[base + t + i * 256] = h;
        AL[base + t + i * 256] = l;
    }
}

// ============================================================================
// Final dual LayerNorm (fp32 in/out)
// ============================================================================
__global__ void __launch_bounds__(128) ln_out_kernel(
    const float* __restrict__ x,
    const float* __restrict__ gt, const float* __restrict__ bt,
    const float* __restrict__ gi, const float* __restrict__ bi,
    float* __restrict__ out)
{
    int row = blockIdx.x;
    int srow = row & (ROWS - 1);
    const float *g, *b;
    if (row < ROWS) { g = gt; b = bt; } else { g = gi; b = bi; }
    const float* src = x + (size_t)srow * DIM;

    int t = threadIdx.x;
    float4 v = ((const float4*)src)[t];
    float s  = v.x + v.y + v.z + v.w;
    float ss = v.x*v.x + v.y*v.y + v.z*v.z + v.w*v.w;

    __shared__ float rs[4], rss[4];
    #pragma unroll
    for (int o = 16; o > 0; o >>= 1) {
        s  += __shfl_xor_sync(0xffffffffu, s,  o);
        ss += __shfl_xor_sync(0xffffffffu, ss, o);
    }
    if ((t & 31) == 0) { rs[t>>5] = s; rss[t>>5] = ss; }
    __syncthreads();
    s  = rs[0] + rs[1] + rs[2] + rs[3];
    ss = rss[0] + rss[1] + rss[2] + rss[3];

    float mu  = s * (1.0f / DIM);
    float var = ss * (1.0f / DIM) - mu * mu;
    float inv = rsqrtf(var + 1e-5f);

    float4 gg = ((const float4*)g)[t];
    float4 bb = ((const float4*)b)[t];
    float4 o4;
    o4.x = (v.x - mu) * inv * gg.x + bb.x;
    o4.y = (v.y - mu) * inv * gg.y + bb.y;
    o4.z = (v.z - mu) * inv * gg.z + bb.z;
    o4.w = (v.w - mu) * inv * gg.w + bb.w;
    ((float4*)(out + (size_t)row * DIM))[t] = o4;
}

// ============================================================================
// mma.sync bf16 split-precision GEMM (BM=128, BN=64, BK=32, 256 thr, 2 CTA/SM)
//   C[M,N] = alpha * (A_hi+A_lo)[M,K] @ B (+ bias)
// LAYOUT 0 (NT): B = [N,K] k-contiguous
// LAYOUT 1 (NN): B = [K,N] n-contiguous (ldmatrix.trans)
// EPI 0: fp32 C | EPI 1: split bf16 CH/CL
// 3 MMA passes: AhBh + AhBl + AlBh, fp32 accumulate.
// ============================================================================
template<int LAYOUT, int EPI>
__global__ void __launch_bounds__(THREADS, 2) mma_gemm_kernel(
    const __nv_bfloat16* __restrict__ AH, const __nv_bfloat16* __restrict__ AL,
    const __nv_bfloat16* __restrict__ BH, const __nv_bfloat16* __restrict__ BL,
    const float* __restrict__ bias,
    float* __restrict__ Cf, __nv_bfloat16* __restrict__ CH, __nv_bfloat16* __restrict__ CL,
    int M, int N, int K, float alpha,
    long long sA, long long sB, long long sC)
{
    extern __shared__ char smem[];
    uint32_t base = smem_to_u32(smem);
    int tid = threadIdx.x, wid = tid >> 5, lane = tid & 31;

    int z = blockIdx.z;
    AH += (size_t)z * sA; AL += (size_t)z * sA;
    BH += (size_t)z * sB; BL += (size_t)z * sB;

    int m0 = blockIdx.y * BM;
    int n0 = blockIdx.x * BN;
    int NK = K / BK;

    auto load_stage = [&](int kt) {
        uint32_t sb = base + (uint32_t)(kt & (STAGES - 1)) * STAGE_BYTES;
        int kb = kt * BK;
        // A: 128 rows x 64B (hi & lo), SW64 swizzle. 512 slots, 2 per thread.
        #pragma unroll
        for (int i = 0; i < 2; i++) {
            int slot = tid + i * THREADS;
            int row = slot >> 2, unit = slot & 3;
            const __nv_bfloat16* gH = AH + (size_t)(m0 + row) * K + kb + unit * 8;
            const __nv_bfloat16* gL = AL + (size_t)(m0 + row) * K + kb + unit * 8;
            uint32_t off = (uint32_t)(row * 64 + unit * 16);
            off ^= (off >> 3) & 0x30;
            CP_A16(sb + OFF_AH + off, gH);
            CP_A16(sb + OFF_AL + off, gL);
        }
        if (LAYOUT == 0) {
            // B NT: 64 rows x 64B. 256 slots, 1 per thread.
            int row = tid >> 2, unit = tid & 3;
            const __nv_bfloat16* gH = BH + (size_t)(n0 + row) * K + kb + unit * 8;
            const __nv_bfloat16* gL = BL + (size_t)(n0 + row) * K + kb + unit * 8;
            uint32_t off = (uint32_t)(row * 64 + unit * 16);
            off ^= (off >> 3) & 0x30;
            CP_A16(sb + OFF_BH + off, gH);
            CP_A16(sb + OFF_BL + off, gL);
        } else {
            // B NN: 32 k-rows x 128B (BN=64 bf16). 256 slots, 1 per thread.
            int row = tid >> 3, unit = tid & 7;
            const __nv_bfloat16* gH = BH + (size_t)(kb + row) * N + n0 + unit * 8;
            const __nv_bfloat16* gL = BL + (size_t)(kb + row) * N + n0 + unit * 8;
            uint32_t off = (uint32_t)(row * 128 + unit * 16);
            off ^= (off >> 3) & 0x70;
            CP_A16(sb + OFF_BH + off, gH);
            CP_A16(sb + OFF_BL + off, gL);
        }
    };

    load_stage(0); CP_COMMIT();
    load_stage(1); CP_COMMIT();
    load_stage(2); CP_COMMIT();

    int wm = wid & 3, wn = wid >> 2;     // 4x2 warp grid, 32x32 warp tile
    float acc[2][4][4];
    #pragma unroll
    for (int a = 0; a < 2; a++)
        #pragma unroll
        for (int b = 0; b < 4; b++)
            #pragma unroll
            for (int c = 0; c < 4; c++) acc[a][b][c] = 0.0f;

    for (int kt = 0; kt < NK; kt++) {
        if (kt + 3 < NK)      { load_stage(kt + 3); CP_COMMIT(); CP_WAIT(3); }
        else if (kt + 2 < NK) { CP_WAIT(2); }
        else if (kt + 1 < NK) { CP_WAIT(1); }
        else                  { CP_WAIT(0); }
        __syncthreads();

        uint32_t sb = base + (uint32_t)(kt & (STAGES - 1)) * STAGE_BYTES;

        #pragma unroll
        for (int ks = 0; ks < 2; ks++) {
            int k0 = ks * 16;

            uint32_t ah[2][4], al[2][4];
            #pragma unroll
            for (int mt = 0; mt < 2; mt++) {
                int row = wm * 32 + mt * 16 + (lane & 15);
                uint32_t off = (uint32_t)(row * 64 + k0 * 2 + ((lane >> 4) << 4));
                off ^= (off >> 3) & 0x30;
                ldm_x4(ah[mt], sb + OFF_AH + off);
                ldm_x4(al[mt], sb + OFF_AL + off);
            }

            uint32_t bh[4][2], bl[4][2];
            if (LAYOUT == 0) {
                #pragma unroll
                for (int p = 0; p < 2; p++) {
                    int nrow = wn * 32 + p * 16 + (lane & 7) + 8 * ((lane >> 4) & 1);
                    uint32_t off = (uint32_t)(nrow * 64 + k0 * 2 + ((lane >> 3) & 1) * 16);
                    off ^= (off >> 3) & 0x30;
                    uint32_t r[4];
                    ldm_x4(r, sb + OFF_BH + off);
                    bh[p*2][0] = r[0]; bh[p*2][1] = r[1];
                    bh[p*2+1][0] = r[2]; bh[p*2+1][1] = r[3];
                    ldm_x4(r, sb + OFF_BL + off);
                    bl[p*2][0] = r[0]; bl[p*2][1] = r[1];
                    bl[p*2+1][0] = r[2]; bl[p*2+1][1] = r[3];
                }
            } else {
                #pragma unroll
                for (int p = 0; p < 2; p++) {
                    int krow = k0 + (lane & 7) + 8 * ((lane >> 3) & 1);
                    int ncol = wn * 32 + p * 16 + 8 * (lane >> 4);
                    uint32_t off = (uint32_t)(krow * 128 + ncol * 2);
                    off ^= (off >> 3) & 0x70;
                    uint32_t r[4];
                    ldm_x4_t(r, sb + OFF_BH + off);
                    bh[p*2][0] = r[0]; bh[p*2][1] = r[1];
                    bh[p*2+1][0] = r[2]; bh[p*2+1][1] = r[3];
                    ldm_x4_t(r, sb + OFF_BL + off);
                    bl[p*2][0] = r[0]; bl[p*2][1] = r[1];
                    bl[p*2+1][0] = r[2]; bl[p*2+1][1] = r[3];
                }
            }

            #pragma unroll
            for (int mt = 0; mt < 2; mt++)
                #pragma unroll
                for (int nt = 0; nt < 4; nt++) {
                    mma_bf16(acc[mt][nt], ah[mt], bh[nt]);
                    mma_bf16(acc[mt][nt], ah[mt], bl[nt]);
                    mma_bf16(acc[mt][nt], al[mt], bh[nt]);
                }
        }
        __syncthreads();
    }

    // ---------------- epilogue ----------------
    #pragma unroll
    for (int mt = 0; mt < 2; mt++) {
        #pragma unroll
        for (int nt = 0; nt < 4; nt++) {
            int m = m0 + wm * 32 + mt * 16 + (lane >> 2);
            int n = n0 + wn * 32 + nt * 8 + (lane & 3) * 2;
            float b0 = bias ? __ldg(&bias[n])     : 0.0f;
            float b1 = bias ? __ldg(&bias[n + 1]) : 0.0f;
            float c0 = alpha * acc[mt][nt][0] + b0;
            float c1 = alpha * acc[mt][nt][1] + b1;
            float c2 = alpha * acc[mt][nt][2] + b0;
            float c3 = alpha * acc[mt][nt][3] + b1;
            if (EPI == 0) {
                float2* p0 = (float2*)(Cf + (size_t)z * sC + (size_t)m * N + n);
                float2* p1 = (float2*)(Cf + (size_t)z * sC + (size_t)(m + 8) * N + n);
                *p0 = make_float2(c0, c1);
                *p1 = make_float2(c2, c3);
            } else {
                __nv_bfloat16 h0,l0,h1,l1,h2,l2,h3,l3;
                split_bf16(c0,h0,l0); split_bf16(c1,h1,l1);
                split_bf16(c2,h2,l2); split_bf16(c3,h3,l3);
                size_t o0 = (size_t)z * sC + (size_t)m * N + n;
                size_t o1 = (size_t)z * sC + (size_t)(m + 8) * N + n;
                *(__nv_bfloat162*)(CH + o0) = __nv_bfloat162(h0, h1);
                *(__nv_bfloat162*)(CL + o0) = __nv_bfloat162(l0, l1);
                *(__nv_bfloat162*)(CH + o1) = __nv_bfloat162(h2, h3);
                *(__nv_bfloat162*)(CL + o1) = __nv_bfloat162(l2, l3);
            }
        }
    }
}

// ============================================================================
// Host orchestration
// ============================================================================
extern "C" void kernel_launch(void* const* d_in, const int* in_sizes, int n_in,
                              void* d_out, int out_size)
{
    const float* text  = (const float*)d_in[0];
    const float* img   = (const float*)d_in[1];
    const float* ln_tg = (const float*)d_in[2];
    const float* ln_tb = (const float*)d_in[3];
    const float* ln_ig = (const float*)d_in[4];
    const float* ln_ib = (const float*)d_in[5];
    const float* Wq  = (const float*)d_in[6];  const float* bq  = (const float*)d_in[7];
    const float* Wkt = (const float*)d_in[8];  const float* bkt = (const float*)d_in[9];
    const float* Wvt = (const float*)d_in[10]; const float* bvt = (const float*)d_in[11];
    const float* Wki = (const float*)d_in[12]; const float* bki = (const float*)d_in[13];
    const float* Wvi = (const float*)d_in[14]; const float* bvi = (const float*)d_in[15];
    const float* Wo  = (const float*)d_in[16]; const float* bo  = (const float*)d_in[17];
    float* out = (float*)d_out;

    static bool attr_done = false;
    if (!attr_done) {
        cudaFuncSetAttribute(mma_gemm_kernel<0,0>, cudaFuncAttributeMaxDynamicSharedMemorySize, SMEM_DYN);
        cudaFuncSetAttribute(mma_gemm_kernel<0,1>, cudaFuncAttributeMaxDynamicSharedMemorySize, SMEM_DYN);
        cudaFuncSetAttribute(mma_gemm_kernel<1,1>, cudaFuncAttributeMaxDynamicSharedMemorySize, SMEM_DYN);
        attr_done = true;
    }

    void *pNH, *pNL, *pQH, *pQL, *pKH, *pKL, *pVH, *pVL, *pATH, *pATL, *pXH, *pXL, *pWH, *pWL, *pS, *pXO;
    cudaGetSymbolAddress(&pNH, g_normsH); cudaGetSymbolAddress(&pNL, g_normsL);
    cudaGetSymbolAddress(&pQH, g_QH);     cudaGetSymbolAddress(&pQL, g_QL);
    cudaGetSymbolAddress(&pKH, g_KH);     cudaGetSymbolAddress(&pKL, g_KL);
    cudaGetSymbolAddress(&pVH, g_VH);     cudaGetSymbolAddress(&pVL, g_VL);
    cudaGetSymbolAddress(&pATH, g_ATH);   cudaGetSymbolAddress(&pATL, g_ATL);
    cudaGetSymbolAddress(&pXH, g_XH);     cudaGetSymbolAddress(&pXL, g_XL);
    cudaGetSymbolAddress(&pWH, g_WH);     cudaGetSymbolAddress(&pWL, g_WL);
    cudaGetSymbolAddress(&pS, g_S);       cudaGetSymbolAddress(&pXO, g_XO);

    __nv_bfloat16* NH = (__nv_bfloat16*)pNH;   __nv_bfloat16* NL = (__nv_bfloat16*)pNL;
    __nv_bfloat16* QH = (__nv_bfloat16*)pQH;   __nv_bfloat16* QL = (__nv_bfloat16*)pQL;
    __nv_bfloat16* KH = (__nv_bfloat16*)pKH;   __nv_bfloat16* KL = (__nv_bfloat16*)pKL;
    __nv_bfloat16* VH = (__nv_bfloat16*)pVH;   __nv_bfloat16* VL = (__nv_bfloat16*)pVL;
    __nv_bfloat16* ATH = (__nv_bfloat16*)pATH; __nv_bfloat16* ATL = (__nv_bfloat16*)pATL;
    __nv_bfloat16* XH = (__nv_bfloat16*)pXH;   __nv_bfloat16* XL = (__nv_bfloat16*)pXL;
    __nv_bfloat16* WH = (__nv_bfloat16*)pWH;   __nv_bfloat16* WL = (__nv_bfloat16*)pWL;
    float* S  = (float*)pS;
    float* XO = (float*)pXO;

    const float scale = 0.04419417382415922f;  // 512^-0.5
    const int HALF = 2 * S_LEN;                // 8192 rows per modality
    const size_t WSZ = (size_t)DIM * DIM;      // 262144

    // 1) input LN + split
    ln_in_split_kernel<<<ROWS, 128>>>(text, img, ln_tg, ln_tb, ln_ig, ln_ib, NH, NL);

    // 2) split weights (order: q, kt, vt, ki, vi, o)
    split_weights_kernel<<<dim3(1024, 6), 256>>>(Wq, Wkt, Wvt, Wki, Wvi, Wo, WH, WL);

    // 3) projections (NT, split bf16 out)
    mma_gemm_kernel<0,1><<<dim3(8, 128, 1), THREADS, SMEM_DYN>>>(
        NH, NL, WH + 0*WSZ, WL + 0*WSZ, bq, nullptr, QH, QL,
        ROWS, DIM, DIM, 1.0f, 0, 0, 0);
    mma_gemm_kernel<0,1><<<dim3(8, 64, 1), THREADS, SMEM_DYN>>>(
        NH, NL, WH + 1*WSZ, WL + 1*WSZ, bkt, nullptr, KH, KL,
        HALF, DIM, DIM, 1.0f, 0, 0, 0);
    mma_gemm_kernel<0,1><<<dim3(8, 64, 1), THREADS, SMEM_DYN>>>(
        NH + (size_t)HALF * DIM, NL + (size_t)HALF * DIM,
        WH + 3*WSZ, WL + 3*WSZ, bki, nullptr,
        KH + (size_t)HALF * DIM, KL + (size_t)HALF * DIM,
        HALF, DIM, DIM, 1.0f, 0, 0, 0);
    mma_gemm_kernel<0,1><<<dim3(8, 64, 1), THREADS, SMEM_DYN>>>(
        NH, NL, WH + 2*WSZ, WL + 2*WSZ, bvt, nullptr, VH, VL,
        HALF, DIM, DIM, 1.0f, 0, 0, 0);
    mma_gemm_kernel<0,1><<<dim3(8, 64, 1), THREADS, SMEM_DYN>>>(
        NH + (size_t)HALF * DIM, NL + (size_t)HALF * DIM,
        WH + 4*WSZ, WL + 4*WSZ, bvi, nullptr,
        VH + (size_t)HALF * DIM, VL + (size_t)HALF * DIM,
        HALF, DIM, DIM, 1.0f, 0, 0, 0);

    // 4) scores = scale * Q @ K^T (batched NT, fp32 out)
    mma_gemm_kernel<0,0><<<dim3(64, 32, NBAT), THREADS, SMEM_DYN>>>(
        QH, QL, KH, KL, nullptr, S, nullptr, nullptr,
        S_LEN, S_LEN, DIM, scale,
        (long long)S_LEN * DIM, (long long)S_LEN * DIM, (long long)S_LEN * S_LEN);

    // 5) softmax + split
    softmax_split_kernel<<<ROWS, 256>>>(S, ATH, ATL);

    // 6) X = attn @ V (batched NN: V natural [seq][dim] layout, split bf16 out)
    mma_gemm_kernel<1,1><<<dim3(8, 32, NBAT), THREADS, SMEM_DYN>>>(
        ATH, ATL, VH, VL, nullptr, nullptr, XH, XL,
        S_LEN, DIM, S_LEN, 1.0f,
        (long long)S_LEN * S_LEN, (long long)S_LEN * DIM, (long long)S_LEN * DIM);

    // 7) XO = X @ Wo^T + bo (NT, fp32 out)
    mma_gemm_kernel<0,0><<<dim3(8, 128, 1), THREADS, SMEM_DYN>>>(
        XH, XL, WH + 5*WSZ, WL + 5*WSZ, bo, XO, nullptr, nullptr,
        ROWS, DIM, DIM, 1.0f, 0, 0, 0);

    // 8) final dual LayerNorm
    ln_out_kernel<<<2 * ROWS, 128>>>(XO, ln_tg, ln_tb, ln_ig, ln_ib, out);
}

// round 7
// speedup vs baseline: 3.1571x; 1.0088x over previous
#include <cuda_runtime.h>
#include <cuda_bf16.h>
#include <cstdint>
#include <math.h>

// ============================================================================
// Problem constants
// ============================================================================
#define DIM   512
#define S_LEN 4096
#define NBAT  4
#define ROWS  (NBAT * S_LEN)      // 16384

// GEMM tiling: BM=128, BN=64, BK=32, 256 threads (8 warps, 4x2 grid, 32x32 warp tile)
#define BM 128
#define BN 64
#define BK 32
#define THREADS 256
#define STAGES 4
// stage layout: AH 8KB | AL 8KB | BH 4KB | BL 4KB = 24KB
#define OFF_AH 0
#define OFF_AL 8192
#define OFF_BH 16384
#define OFF_BL 20480
#define STAGE_BYTES 24576
#define SMEM_DYN (STAGES * STAGE_BYTES)   // 98304

// ============================================================================
// PTX helpers (plain sm_103-legal: cp.async / ldmatrix / mma.sync only)
// ============================================================================
__device__ __forceinline__ uint32_t smem_to_u32(const void* p) {
    uint32_t a;
    asm("{ .reg .u64 t; cvta.to.shared.u64 t, %1; cvt.u32.u64 %0, t; }" : "=r"(a) : "l"(p));
    return a;
}
#define CP_A16(s, g) \
    asm volatile("cp.async.cg.shared.global [%0], [%1], 16;" :: "r"(s), "l"(g))
#define CP_COMMIT() asm volatile("cp.async.commit_group;" ::: "memory")
#define CP_WAIT(n)  asm volatile("cp.async.wait_group %0;" :: "n"(n) : "memory")

__device__ __forceinline__ void ldm_x4(uint32_t* r, uint32_t addr) {
    asm volatile("ldmatrix.sync.aligned.m8n8.x4.shared.b16 {%0,%1,%2,%3}, [%4];"
        : "=r"(r[0]), "=r"(r[1]), "=r"(r[2]), "=r"(r[3]) : "r"(addr));
}
__device__ __forceinline__ void ldm_x4_t(uint32_t* r, uint32_t addr) {
    asm volatile("ldmatrix.sync.aligned.m8n8.x4.trans.shared.b16 {%0,%1,%2,%3}, [%4];"
        : "=r"(r[0]), "=r"(r[1]), "=r"(r[2]), "=r"(r[3]) : "r"(addr));
}
__device__ __forceinline__ void mma_bf16(float* d, const uint32_t* a, const uint32_t* b) {
    asm volatile("mma.sync.aligned.m16n8k16.row.col.f32.bf16.bf16.f32 "
        "{%0,%1,%2,%3}, {%4,%5,%6,%7}, {%8,%9}, {%0,%1,%2,%3};"
        : "+f"(d[0]), "+f"(d[1]), "+f"(d[2]), "+f"(d[3])
        : "r"(a[0]), "r"(a[1]), "r"(a[2]), "r"(a[3]), "r"(b[0]), "r"(b[1]));
}

__device__ __forceinline__ void split_bf16(float v, __nv_bfloat16& h, __nv_bfloat16& l) {
    h = __float2bfloat16(v);
    l = __float2bfloat16(v - __bfloat162float(h));
}

// ============================================================================
// Scratch buffers
// ============================================================================
__device__ __align__(128) __nv_bfloat16 g_normsH[(size_t)ROWS * DIM];
__device__ __align__(128) __nv_bfloat16 g_normsL[(size_t)ROWS * DIM];
__device__ __align__(128) __nv_bfloat16 g_QH[(size_t)ROWS * DIM];
__device__ __align__(128) __nv_bfloat16 g_QL[(size_t)ROWS * DIM];
__device__ __align__(128) __nv_bfloat16 g_KH[(size_t)ROWS * DIM];
__device__ __align__(128) __nv_bfloat16 g_KL[(size_t)ROWS * DIM];
__device__ __align__(128) __nv_bfloat16 g_VH[(size_t)ROWS * DIM];
__device__ __align__(128) __nv_bfloat16 g_VL[(size_t)ROWS * DIM];
__device__ __align__(128) __nv_bfloat16 g_EH[(size_t)NBAT * S_LEN * S_LEN];  // exp(scores) hi
__device__ __align__(128) __nv_bfloat16 g_EL[(size_t)NBAT * S_LEN * S_LEN];  // exp(scores) lo
__device__ __align__(128) __nv_bfloat16 g_XH[(size_t)ROWS * DIM];
__device__ __align__(128) __nv_bfloat16 g_XL[(size_t)ROWS * DIM];
__device__ __align__(128) __nv_bfloat16 g_WH[(size_t)6 * DIM * DIM];
__device__ __align__(128) __nv_bfloat16 g_WL[(size_t)6 * DIM * DIM];
__device__ __align__(128) float g_rhoInv[(size_t)ROWS];   // 1 / rowsum(exp(scores))
__device__ __align__(128) float g_XO[(size_t)ROWS * DIM];

// ============================================================================
// Input LayerNorm -> split bf16 norms
// ============================================================================
__global__ void __launch_bounds__(128) ln_in_split_kernel(
    const float* __restrict__ text, const float* __restrict__ img,
    const float* __restrict__ gt, const float* __restrict__ bt,
    const float* __restrict__ gi, const float* __restrict__ bi,
    __nv_bfloat16* __restrict__ outH, __nv_bfloat16* __restrict__ outL)
{
    int row = blockIdx.x;
    const float *src, *g, *b;
    if (row < 2 * S_LEN) { src = text + (size_t)row * DIM;              g = gt; b = bt; }
    else                 { src = img  + (size_t)(row - 2*S_LEN) * DIM;  g = gi; b = bi; }

    int t = threadIdx.x;
    float4 x = ((const float4*)src)[t];
    float s  = x.x + x.y + x.z + x.w;
    float ss = x.x*x.x + x.y*x.y + x.z*x.z + x.w*x.w;

    __shared__ float rs[4], rss[4];
    #pragma unroll
    for (int o = 16; o > 0; o >>= 1) {
        s  += __shfl_xor_sync(0xffffffffu, s,  o);
        ss += __shfl_xor_sync(0xffffffffu, ss, o);
    }
    if ((t & 31) == 0) { rs[t>>5] = s; rss[t>>5] = ss; }
    __syncthreads();
    s  = rs[0] + rs[1] + rs[2] + rs[3];
    ss = rss[0] + rss[1] + rss[2] + rss[3];

    float mu  = s * (1.0f / DIM);
    float var = ss * (1.0f / DIM) - mu * mu;
    float inv = rsqrtf(var + 1e-5f);

    float4 gg = ((const float4*)g)[t];
    float4 bb = ((const float4*)b)[t];
    float v0 = (x.x - mu) * inv * gg.x + bb.x;
    float v1 = (x.y - mu) * inv * gg.y + bb.y;
    float v2 = (x.z - mu) * inv * gg.z + bb.z;
    float v3 = (x.w - mu) * inv * gg.w + bb.w;

    size_t base = (size_t)row * DIM + t * 4;
    __nv_bfloat16 h0,h1,h2,h3,l0,l1,l2,l3;
    split_bf16(v0,h0,l0); split_bf16(v1,h1,l1); split_bf16(v2,h2,l2); split_bf16(v3,h3,l3);
    ((__nv_bfloat162*)(outH + base))[0] = __nv_bfloat162(h0, h1);
    ((__nv_bfloat162*)(outH + base))[1] = __nv_bfloat162(h2, h3);
    ((__nv_bfloat162*)(outL + base))[0] = __nv_bfloat162(l0, l1);
    ((__nv_bfloat162*)(outL + base))[1] = __nv_bfloat162(l2, l3);
}

// ============================================================================
// Split 6 weight matrices into hi/lo bf16
// ============================================================================
__global__ void __launch_bounds__(256) split_weights_kernel(
    const float* __restrict__ w0, const float* __restrict__ w1,
    const float* __restrict__ w2, const float* __restrict__ w3,
    const float* __restrict__ w4, const float* __restrict__ w5,
    __nv_bfloat16* __restrict__ WH, __nv_bfloat16* __restrict__ WL)
{
    int mat = blockIdx.y;
    const float* ws[6] = {w0, w1, w2, w3, w4, w5};
    const float* w = ws[mat];
    int i = blockIdx.x * 256 + threadIdx.x;
    float v = w[i];
    __nv_bfloat16 h, l;
    split_bf16(v, h, l);
    size_t o = (size_t)mat * DIM * DIM + i;
    WH[o] = h; WL[o] = l;
}

// ============================================================================
// Row sums of EH -> 1/rho (deterministic tree reduce).
// One block per row; reads bf16 hi part only (3e-5 uniform row-scale error,
// cancelled by the final LayerNorm's scale invariance).
// ============================================================================
__global__ void __launch_bounds__(256) rowsum_inv_kernel(
    const __nv_bfloat16* __restrict__ EH, float* __restrict__ rhoInv)
{
    size_t row = blockIdx.x;
    const __nv_bfloat162* p = (const __nv_bfloat162*)(EH + row * S_LEN);
    int t = threadIdx.x;

    float sum = 0.0f;
    #pragma unroll
    for (int j = 0; j < 8; j++) {
        __nv_bfloat162 v = p[t + j * 256];
        sum += __bfloat162float(v.x) + __bfloat162float(v.y);
    }
    __shared__ float red[8];
    #pragma unroll
    for (int o = 16; o > 0; o >>= 1) sum += __shfl_xor_sync(0xffffffffu, sum, o);
    if ((t & 31) == 0) red[t >> 5] = sum;
    __syncthreads();
    if (t == 0) {
        float tot = red[0] + red[1] + red[2] + red[3] + red[4] + red[5] + red[6] + red[7];
        rhoInv[row] = 1.0f / tot;
    }
}

// ============================================================================
// Final dual LayerNorm (fp32 in/out)
// ============================================================================
__global__ void __launch_bounds__(128) ln_out_kernel(
    const float* __restrict__ x,
    const float* __restrict__ gt, const float* __restrict__ bt,
    const float* __restrict__ gi, const float* __restrict__ bi,
    float* __restrict__ out)
{
    int row = blockIdx.x;
    int srow = row & (ROWS - 1);
    const float *g, *b;
    if (row < ROWS) { g = gt; b = bt; } else { g = gi; b = bi; }
    const float* src = x + (size_t)srow * DIM;

    int t = threadIdx.x;
    float4 v = ((const float4*)src)[t];
    float s  = v.x + v.y + v.z + v.w;
    float ss = v.x*v.x + v.y*v.y + v.z*v.z + v.w*v.w;

    __shared__ float rs[4], rss[4];
    #pragma unroll
    for (int o = 16; o > 0; o >>= 1) {
        s  += __shfl_xor_sync(0xffffffffu, s,  o);
        ss += __shfl_xor_sync(0xffffffffu, ss, o);
    }
    if ((t & 31) == 0) { rs[t>>5] = s; rss[t>>5] = ss; }
    __syncthreads();
    s  = rs[0] + rs[1] + rs[2] + rs[3];
    ss = rss[0] + rss[1] + rss[2] + rss[3];

    float mu  = s * (1.0f / DIM);
    float var = ss * (1.0f / DIM) - mu * mu;
    float inv = rsqrtf(var + 1e-5f);

    float4 gg = ((const float4*)g)[t];
    float4 bb = ((const float4*)b)[t];
    float4 o4;
    o4.x = (v.x - mu) * inv * gg.x + bb.x;
    o4.y = (v.y - mu) * inv * gg.y + bb.y;
    o4.z = (v.z - mu) * inv * gg.z + bb.z;
    o4.w = (v.w - mu) * inv * gg.w + bb.w;
    ((float4*)(out + (size_t)row * DIM))[t] = o4;
}

// ============================================================================
// mma.sync bf16 split-precision GEMM (BM=128, BN=64, BK=32, 256 thr, 2 CTA/SM)
//   C[M,N] = f( alpha * (A_hi+A_lo)[M,K] @ B ) (+ bias)
// LAYOUT 0 (NT): B = [N,K] k-contiguous
// LAYOUT 1 (NN): B = [K,N] n-contiguous (ldmatrix.trans)
// EPI 0: fp32 C (alpha + bias)
// EPI 1: split bf16 CH/CL (alpha + bias)
// EPI 2: split bf16 CH/CL = exp(alpha * acc)           [scores -> unnorm softmax]
// EPI 3: split bf16 CH/CL = acc * rscale[z*M + m]      [PV -> normalized X]
// 3 MMA passes: AhBh + AhBl + AlBh, fp32 accumulate.
// ============================================================================
template<int LAYOUT, int EPI>
__global__ void __launch_bounds__(THREADS, 2) mma_gemm_kernel(
    const __nv_bfloat16* __restrict__ AH, const __nv_bfloat16* __restrict__ AL,
    const __nv_bfloat16* __restrict__ BH, const __nv_bfloat16* __restrict__ BL,
    const float* __restrict__ bias, const float* __restrict__ rscale,
    float* __restrict__ Cf, __nv_bfloat16* __restrict__ CH, __nv_bfloat16* __restrict__ CL,
    int M, int N, int K, float alpha,
    long long sA, long long sB, long long sC)
{
    extern __shared__ char smem[];
    uint32_t base = smem_to_u32(smem);
    int tid = threadIdx.x, wid = tid >> 5, lane = tid & 31;

    int z = blockIdx.z;
    AH += (size_t)z * sA; AL += (size_t)z * sA;
    BH += (size_t)z * sB; BL += (size_t)z * sB;

    int m0 = blockIdx.y * BM;
    int n0 = blockIdx.x * BN;
    int NK = K / BK;

    auto load_stage = [&](int kt) {
        uint32_t sb = base + (uint32_t)(kt & (STAGES - 1)) * STAGE_BYTES;
        int kb = kt * BK;
        // A: 128 rows x 64B (hi & lo), SW64 swizzle. 512 slots, 2 per thread.
        #pragma unroll
        for (int i = 0; i < 2; i++) {
            int slot = tid + i * THREADS;
            int row = slot >> 2, unit = slot & 3;
            const __nv_bfloat16* gH = AH + (size_t)(m0 + row) * K + kb + unit * 8;
            const __nv_bfloat16* gL = AL + (size_t)(m0 + row) * K + kb + unit * 8;
            uint32_t off = (uint32_t)(row * 64 + unit * 16);
            off ^= (off >> 3) & 0x30;
            CP_A16(sb + OFF_AH + off, gH);
            CP_A16(sb + OFF_AL + off, gL);
        }
        if (LAYOUT == 0) {
            // B NT: 64 rows x 64B. 256 slots, 1 per thread.
            int row = tid >> 2, unit = tid & 3;
            const __nv_bfloat16* gH = BH + (size_t)(n0 + row) * K + kb + unit * 8;
            const __nv_bfloat16* gL = BL + (size_t)(n0 + row) * K + kb + unit * 8;
            uint32_t off = (uint32_t)(row * 64 + unit * 16);
            off ^= (off >> 3) & 0x30;
            CP_A16(sb + OFF_BH + off, gH);
            CP_A16(sb + OFF_BL + off, gL);
        } else {
            // B NN: 32 k-rows x 128B (BN=64 bf16). 256 slots, 1 per thread.
            int row = tid >> 3, unit = tid & 7;
            const __nv_bfloat16* gH = BH + (size_t)(kb + row) * N + n0 + unit * 8;
            const __nv_bfloat16* gL = BL + (size_t)(kb + row) * N + n0 + unit * 8;
            uint32_t off = (uint32_t)(row * 128 + unit * 16);
            off ^= (off >> 3) & 0x70;
            CP_A16(sb + OFF_BH + off, gH);
            CP_A16(sb + OFF_BL + off, gL);
        }
    };

    load_stage(0); CP_COMMIT();
    load_stage(1); CP_COMMIT();
    load_stage(2); CP_COMMIT();

    int wm = wid & 3, wn = wid >> 2;     // 4x2 warp grid, 32x32 warp tile
    float acc[2][4][4];
    #pragma unroll
    for (int a = 0; a < 2; a++)
        #pragma unroll
        for (int b = 0; b < 4; b++)
            #pragma unroll
            for (int c = 0; c < 4; c++) acc[a][b][c] = 0.0f;

    for (int kt = 0; kt < NK; kt++) {
        if (kt + 3 < NK)      { load_stage(kt + 3); CP_COMMIT(); CP_WAIT(3); }
        else if (kt + 2 < NK) { CP_WAIT(2); }
        else if (kt + 1 < NK) { CP_WAIT(1); }
        else                  { CP_WAIT(0); }
        __syncthreads();

        uint32_t sb = base + (uint32_t)(kt & (STAGES - 1)) * STAGE_BYTES;

        #pragma unroll
        for (int ks = 0; ks < 2; ks++) {
            int k0 = ks * 16;

            uint32_t ah[2][4], al[2][4];
            #pragma unroll
            for (int mt = 0; mt < 2; mt++) {
                int row = wm * 32 + mt * 16 + (lane & 15);
                uint32_t off = (uint32_t)(row * 64 + k0 * 2 + ((lane >> 4) << 4));
                off ^= (off >> 3) & 0x30;
                ldm_x4(ah[mt], sb + OFF_AH + off);
                ldm_x4(al[mt], sb + OFF_AL + off);
            }

            uint32_t bh[4][2], bl[4][2];
            if (LAYOUT == 0) {
                #pragma unroll
                for (int p = 0; p < 2; p++) {
                    int nrow = wn * 32 + p * 16 + (lane & 7) + 8 * ((lane >> 4) & 1);
                    uint32_t off = (uint32_t)(nrow * 64 + k0 * 2 + ((lane >> 3) & 1) * 16);
                    off ^= (off >> 3) & 0x30;
                    uint32_t r[4];
                    ldm_x4(r, sb + OFF_BH + off);
                    bh[p*2][0] = r[0]; bh[p*2][1] = r[1];
                    bh[p*2+1][0] = r[2]; bh[p*2+1][1] = r[3];
                    ldm_x4(r, sb + OFF_BL + off);
                    bl[p*2][0] = r[0]; bl[p*2][1] = r[1];
                    bl[p*2+1][0] = r[2]; bl[p*2+1][1] = r[3];
                }
            } else {
                #pragma unroll
                for (int p = 0; p < 2; p++) {
                    int krow = k0 + (lane & 7) + 8 * ((lane >> 3) & 1);
                    int ncol = wn * 32 + p * 16 + 8 * (lane >> 4);
                    uint32_t off = (uint32_t)(krow * 128 + ncol * 2);
                    off ^= (off >> 3) & 0x70;
                    uint32_t r[4];
                    ldm_x4_t(r, sb + OFF_BH + off);
                    bh[p*2][0] = r[0]; bh[p*2][1] = r[1];
                    bh[p*2+1][0] = r[2]; bh[p*2+1][1] = r[3];
                    ldm_x4_t(r, sb + OFF_BL + off);
                    bl[p*2][0] = r[0]; bl[p*2][1] = r[1];
                    bl[p*2+1][0] = r[2]; bl[p*2+1][1] = r[3];
                }
            }

            #pragma unroll
            for (int mt = 0; mt < 2; mt++)
                #pragma unroll
                for (int nt = 0; nt < 4; nt++) {
                    mma_bf16(acc[mt][nt], ah[mt], bh[nt]);
                    mma_bf16(acc[mt][nt], ah[mt], bl[nt]);
                    mma_bf16(acc[mt][nt], al[mt], bh[nt]);
                }
        }
        __syncthreads();
    }

    // ---------------- epilogue ----------------
    #pragma unroll
    for (int mt = 0; mt < 2; mt++) {
        int mrow = m0 + wm * 32 + mt * 16 + (lane >> 2);
        float rs0 = 1.0f, rs1 = 1.0f;
        if (EPI == 3) {
            rs0 = __ldg(&rscale[(size_t)z * M + mrow]);
            rs1 = __ldg(&rscale[(size_t)z * M + mrow + 8]);
        }
        #pragma unroll
        for (int nt = 0; nt < 4; nt++) {
            int m = mrow;
            int n = n0 + wn * 32 + nt * 8 + (lane & 3) * 2;
            float c0, c1, c2, c3;
            if (EPI == 0 || EPI == 1) {
                float b0 = bias ? __ldg(&bias[n])     : 0.0f;
                float b1 = bias ? __ldg(&bias[n + 1]) : 0.0f;
                c0 = alpha * acc[mt][nt][0] + b0;
                c1 = alpha * acc[mt][nt][1] + b1;
                c2 = alpha * acc[mt][nt][2] + b0;
                c3 = alpha * acc[mt][nt][3] + b1;
            } else if (EPI == 2) {
                c0 = __expf(alpha * acc[mt][nt][0]);
                c1 = __expf(alpha * acc[mt][nt][1]);
                c2 = __expf(alpha * acc[mt][nt][2]);
                c3 = __expf(alpha * acc[mt][nt][3]);
            } else {  // EPI == 3
                c0 = acc[mt][nt][0] * rs0;
                c1 = acc[mt][nt][1] * rs0;
                c2 = acc[mt][nt][2] * rs1;
                c3 = acc[mt][nt][3] * rs1;
            }
            if (EPI == 0) {
                float2* p0 = (float2*)(Cf + (size_t)z * sC + (size_t)m * N + n);
                float2* p1 = (float2*)(Cf + (size_t)z * sC + (size_t)(m + 8) * N + n);
                *p0 = make_float2(c0, c1);
                *p1 = make_float2(c2, c3);
            } else {
                __nv_bfloat16 h0,l0,h1,l1,h2,l2,h3,l3;
                split_bf16(c0,h0,l0); split_bf16(c1,h1,l1);
                split_bf16(c2,h2,l2); split_bf16(c3,h3,l3);
                size_t o0 = (size_t)z * sC + (size_t)m * N + n;
                size_t o1 = (size_t)z * sC + (size_t)(m + 8) * N + n;
                *(__nv_bfloat162*)(CH + o0) = __nv_bfloat162(h0, h1);
                *(__nv_bfloat162*)(CL + o0) = __nv_bfloat162(l0, l1);
                *(__nv_bfloat162*)(CH + o1) = __nv_bfloat162(h2, h3);
                *(__nv_bfloat162*)(CL + o1) = __nv_bfloat162(l2, l3);
            }
        }
    }
}

// ============================================================================
// Host orchestration
// ============================================================================
extern "C" void kernel_launch(void* const* d_in, const int* in_sizes, int n_in,
                              void* d_out, int out_size)
{
    const float* text  = (const float*)d_in[0];
    const float* img   = (const float*)d_in[1];
    const float* ln_tg = (const float*)d_in[2];
    const float* ln_tb = (const float*)d_in[3];
    const float* ln_ig = (const float*)d_in[4];
    const float* ln_ib = (const float*)d_in[5];
    const float* Wq  = (const float*)d_in[6];  const float* bq  = (const float*)d_in[7];
    const float* Wkt = (const float*)d_in[8];  const float* bkt = (const float*)d_in[9];
    const float* Wvt = (const float*)d_in[10]; const float* bvt = (const float*)d_in[11];
    const float* Wki = (const float*)d_in[12]; const float* bki = (const float*)d_in[13];
    const float* Wvi = (const float*)d_in[14]; const float* bvi = (const float*)d_in[15];
    const float* Wo  = (const float*)d_in[16]; const float* bo  = (const float*)d_in[17];
    float* out = (float*)d_out;

    static bool attr_done = false;
    if (!attr_done) {
        cudaFuncSetAttribute(mma_gemm_kernel<0,0>, cudaFuncAttributeMaxDynamicSharedMemorySize, SMEM_DYN);
        cudaFuncSetAttribute(mma_gemm_kernel<0,1>, cudaFuncAttributeMaxDynamicSharedMemorySize, SMEM_DYN);
        cudaFuncSetAttribute(mma_gemm_kernel<0,2>, cudaFuncAttributeMaxDynamicSharedMemorySize, SMEM_DYN);
        cudaFuncSetAttribute(mma_gemm_kernel<1,3>, cudaFuncAttributeMaxDynamicSharedMemorySize, SMEM_DYN);
        attr_done = true;
    }

    void *pNH, *pNL, *pQH, *pQL, *pKH, *pKL, *pVH, *pVL, *pEH, *pEL, *pXH, *pXL, *pWH, *pWL, *pRI, *pXO;
    cudaGetSymbolAddress(&pNH, g_normsH); cudaGetSymbolAddress(&pNL, g_normsL);
    cudaGetSymbolAddress(&pQH, g_QH);     cudaGetSymbolAddress(&pQL, g_QL);
    cudaGetSymbolAddress(&pKH, g_KH);     cudaGetSymbolAddress(&pKL, g_KL);
    cudaGetSymbolAddress(&pVH, g_VH);     cudaGetSymbolAddress(&pVL, g_VL);
    cudaGetSymbolAddress(&pEH, g_EH);     cudaGetSymbolAddress(&pEL, g_EL);
    cudaGetSymbolAddress(&pXH, g_XH);     cudaGetSymbolAddress(&pXL, g_XL);
    cudaGetSymbolAddress(&pWH, g_WH);     cudaGetSymbolAddress(&pWL, g_WL);
    cudaGetSymbolAddress(&pRI, g_rhoInv); cudaGetSymbolAddress(&pXO, g_XO);

    __nv_bfloat16* NH = (__nv_bfloat16*)pNH;   __nv_bfloat16* NL = (__nv_bfloat16*)pNL;
    __nv_bfloat16* QH = (__nv_bfloat16*)pQH;   __nv_bfloat16* QL = (__nv_bfloat16*)pQL;
    __nv_bfloat16* KH = (__nv_bfloat16*)pKH;   __nv_bfloat16* KL = (__nv_bfloat16*)pKL;
    __nv_bfloat16* VH = (__nv_bfloat16*)pVH;   __nv_bfloat16* VL = (__nv_bfloat16*)pVL;
    __nv_bfloat16* EH = (__nv_bfloat16*)pEH;   __nv_bfloat16* EL = (__nv_bfloat16*)pEL;
    __nv_bfloat16* XH = (__nv_bfloat16*)pXH;   __nv_bfloat16* XL = (__nv_bfloat16*)pXL;
    __nv_bfloat16* WH = (__nv_bfloat16*)pWH;   __nv_bfloat16* WL = (__nv_bfloat16*)pWL;
    float* RI = (float*)pRI;
    float* XO = (float*)pXO;

    const float scale = 0.04419417382415922f;  // 512^-0.5
    const int HALF = 2 * S_LEN;                // 8192 rows per modality
    const size_t WSZ = (size_t)DIM * DIM;      // 262144

    // 1) input LN + split
    ln_in_split_kernel<<<ROWS, 128>>>(text, img, ln_tg, ln_tb, ln_ig, ln_ib, NH, NL);

    // 2) split weights (order: q, kt, vt, ki, vi, o)
    split_weights_kernel<<<dim3(1024, 6), 256>>>(Wq, Wkt, Wvt, Wki, Wvi, Wo, WH, WL);

    // 3) projections (NT, split bf16 out)
    mma_gemm_kernel<0,1><<<dim3(8, 128, 1), THREADS, SMEM_DYN>>>(
        NH, NL, WH + 0*WSZ, WL + 0*WSZ, bq, nullptr, nullptr, QH, QL,
        ROWS, DIM, DIM, 1.0f, 0, 0, 0);
    mma_gemm_kernel<0,1><<<dim3(8, 64, 1), THREADS, SMEM_DYN>>>(
        NH, NL, WH + 1*WSZ, WL + 1*WSZ, bkt, nullptr, nullptr, KH, KL,
        HALF, DIM, DIM, 1.0f, 0, 0, 0);
    mma_gemm_kernel<0,1><<<dim3(8, 64, 1), THREADS, SMEM_DYN>>>(
        NH + (size_t)HALF * DIM, NL + (size_t)HALF * DIM,
        WH + 3*WSZ, WL + 3*WSZ, bki, nullptr, nullptr,
        KH + (size_t)HALF * DIM, KL + (size_t)HALF * DIM,
        HALF, DIM, DIM, 1.0f, 0, 0, 0);
    mma_gemm_kernel<0,1><<<dim3(8, 64, 1), THREADS, SMEM_DYN>>>(
        NH, NL, WH + 2*WSZ, WL + 2*WSZ, bvt, nullptr, nullptr, VH, VL,
        HALF, DIM, DIM, 1.0f, 0, 0, 0);
    mma_gemm_kernel<0,1><<<dim3(8, 64, 1), THREADS, SMEM_DYN>>>(
        NH + (size_t)HALF * DIM, NL + (size_t)HALF * DIM,
        WH + 4*WSZ, WL + 4*WSZ, bvi, nullptr, nullptr,
        VH + (size_t)HALF * DIM, VL + (size_t)HALF * DIM,
        HALF, DIM, DIM, 1.0f, 0, 0, 0);

    // 4) E = exp(scale * Q @ K^T) (batched NT, split bf16 out, no max subtraction)
    mma_gemm_kernel<0,2><<<dim3(64, 32, NBAT), THREADS, SMEM_DYN>>>(
        QH, QL, KH, KL, nullptr, nullptr, nullptr, EH, EL,
        S_LEN, S_LEN, DIM, scale,
        (long long)S_LEN * DIM, (long long)S_LEN * DIM, (long long)S_LEN * S_LEN);

    // 5) rho^-1 = 1 / rowsum(EH)
    rowsum_inv_kernel<<<ROWS, 256>>>(EH, RI);

    // 6) X = (E @ V) * rho^-1 (batched NN, split bf16 out)
    mma_gemm_kernel<1,3><<<dim3(8, 32, NBAT), THREADS, SMEM_DYN>>>(
        EH, EL, VH, VL, nullptr, RI, nullptr, XH, XL,
        S_LEN, DIM, S_LEN, 1.0f,
        (long long)S_LEN * S_LEN, (long long)S_LEN * DIM, (long long)S_LEN * DIM);

    // 7) XO = X @ Wo^T + bo (NT, fp32 out)
    mma_gemm_kernel<0,0><<<dim3(8, 128, 1), THREADS, SMEM_DYN>>>(
        XH, XL, WH + 5*WSZ, WL + 5*WSZ, bo, nullptr, XO, nullptr, nullptr,
        ROWS, DIM, DIM, 1.0f, 0, 0, 0);

    // 8) final dual LayerNorm
    ln_out_kernel<<<2 * ROWS, 128>>>(XO, ln_tg, ln_tb, ln_ig, ln_ib, out);
}

// round 9
// speedup vs baseline: 5.3225x; 1.6859x over previous
#include <cuda_runtime.h>
#include <cuda_fp16.h>
#include <cstdint>
#include <math.h>

// ============================================================================
// Problem constants
// ============================================================================
#define DIM   512
#define S_LEN 4096
#define NBAT  4
#define ROWS  (NBAT * S_LEN)      // 16384

// GEMM tiling: BM=128, BN=64, BK=32, 256 threads (8 warps, 4x2 grid, 32x32 warp tile)
#define BM 128
#define BN 64
#define BK 32
#define THREADS 256
#define STAGES 4
#define SMEM_N3 98304   // 4 stages * 24KB (3-pass: AH,AL,BH,BL)
#define SMEM_N1 49152   // 4 stages * 12KB (1-pass: AH,BH)

// ============================================================================
// PTX helpers (plain sm_103-legal: cp.async / ldmatrix / mma.sync only)
// ============================================================================
__device__ __forceinline__ uint32_t smem_to_u32(const void* p) {
    uint32_t a;
    asm("{ .reg .u64 t; cvta.to.shared.u64 t, %1; cvt.u32.u64 %0, t; }" : "=r"(a) : "l"(p));
    return a;
}
#define CP_A16(s, g) \
    asm volatile("cp.async.cg.shared.global [%0], [%1], 16;" :: "r"(s), "l"(g))
#define CP_COMMIT() asm volatile("cp.async.commit_group;" ::: "memory")
#define CP_WAIT(n)  asm volatile("cp.async.wait_group %0;" :: "n"(n) : "memory")

__device__ __forceinline__ void ldm_x4(uint32_t* r, uint32_t addr) {
    asm volatile("ldmatrix.sync.aligned.m8n8.x4.shared.b16 {%0,%1,%2,%3}, [%4];"
        : "=r"(r[0]), "=r"(r[1]), "=r"(r[2]), "=r"(r[3]) : "r"(addr));
}
__device__ __forceinline__ void ldm_x4_t(uint32_t* r, uint32_t addr) {
    asm volatile("ldmatrix.sync.aligned.m8n8.x4.trans.shared.b16 {%0,%1,%2,%3}, [%4];"
        : "=r"(r[0]), "=r"(r[1]), "=r"(r[2]), "=r"(r[3]) : "r"(addr));
}
__device__ __forceinline__ void mma_f16(float* d, const uint32_t* a, const uint32_t* b) {
    asm volatile("mma.sync.aligned.m16n8k16.row.col.f32.f16.f16.f32 "
        "{%0,%1,%2,%3}, {%4,%5,%6,%7}, {%8,%9}, {%0,%1,%2,%3};"
        : "+f"(d[0]), "+f"(d[1]), "+f"(d[2]), "+f"(d[3])
        : "r"(a[0]), "r"(a[1]), "r"(a[2]), "r"(a[3]), "r"(b[0]), "r"(b[1]));
}

__device__ __forceinline__ void split_f16(float v, __half& h, __half& l) {
    h = __float2half(v);
    l = __float2half(v - __half2float(h));
}

// ============================================================================
// Scratch buffers
// ============================================================================
__device__ __align__(128) __half g_normsH[(size_t)ROWS * DIM];
__device__ __align__(128) __half g_normsL[(size_t)ROWS * DIM];
__device__ __align__(128) __half g_Q[(size_t)ROWS * DIM];
__device__ __align__(128) __half g_K[(size_t)ROWS * DIM];
__device__ __align__(128) __half g_V[(size_t)ROWS * DIM];
__device__ __align__(128) __half g_E[(size_t)NBAT * S_LEN * S_LEN];   // exp(scores), fp16
__device__ __align__(128) __half g_XH[(size_t)ROWS * DIM];
__device__ __align__(128) __half g_XL[(size_t)ROWS * DIM];
__device__ __align__(128) __half g_WH[(size_t)6 * DIM * DIM];
__device__ __align__(128) __half g_WL[(size_t)6 * DIM * DIM];
__device__ __align__(128) float g_rhoInv[(size_t)ROWS];
__device__ __align__(128) float g_XO[(size_t)ROWS * DIM];

// ============================================================================
// Input LayerNorm -> split fp16 norms
// ============================================================================
__global__ void __launch_bounds__(128) ln_in_split_kernel(
    const float* __restrict__ text, const float* __restrict__ img,
    const float* __restrict__ gt, const float* __restrict__ bt,
    const float* __restrict__ gi, const float* __restrict__ bi,
    __half* __restrict__ outH, __half* __restrict__ outL)
{
    int row = blockIdx.x;
    const float *src, *g, *b;
    if (row < 2 * S_LEN) { src = text + (size_t)row * DIM;              g = gt; b = bt; }
    else                 { src = img  + (size_t)(row - 2*S_LEN) * DIM;  g = gi; b = bi; }

    int t = threadIdx.x;
    float4 x = ((const float4*)src)[t];
    float s  = x.x + x.y + x.z + x.w;
    float ss = x.x*x.x + x.y*x.y + x.z*x.z + x.w*x.w;

    __shared__ float rs[4], rss[4];
    #pragma unroll
    for (int o = 16; o > 0; o >>= 1) {
        s  += __shfl_xor_sync(0xffffffffu, s,  o);
        ss += __shfl_xor_sync(0xffffffffu, ss, o);
    }
    if ((t & 31) == 0) { rs[t>>5] = s; rss[t>>5] = ss; }
    __syncthreads();
    s  = rs[0] + rs[1] + rs[2] + rs[3];
    ss = rss[0] + rss[1] + rss[2] + rss[3];

    float mu  = s * (1.0f / DIM);
    float var = ss * (1.0f / DIM) - mu * mu;
    float inv = rsqrtf(var + 1e-5f);

    float4 gg = ((const float4*)g)[t];
    float4 bb = ((const float4*)b)[t];
    float v0 = (x.x - mu) * inv * gg.x + bb.x;
    float v1 = (x.y - mu) * inv * gg.y + bb.y;
    float v2 = (x.z - mu) * inv * gg.z + bb.z;
    float v3 = (x.w - mu) * inv * gg.w + bb.w;

    size_t base = (size_t)row * DIM + t * 4;
    __half h0,h1,h2,h3,l0,l1,l2,l3;
    split_f16(v0,h0,l0); split_f16(v1,h1,l1); split_f16(v2,h2,l2); split_f16(v3,h3,l3);
    ((__half2*)(outH + base))[0] = __halves2half2(h0, h1);
    ((__half2*)(outH + base))[1] = __halves2half2(h2, h3);
    ((__half2*)(outL + base))[0] = __halves2half2(l0, l1);
    ((__half2*)(outL + base))[1] = __halves2half2(l2, l3);
}

// ============================================================================
// Split 6 weight matrices into hi/lo fp16
// ============================================================================
__global__ void __launch_bounds__(256) split_weights_kernel(
    const float* __restrict__ w0, const float* __restrict__ w1,
    const float* __restrict__ w2, const float* __restrict__ w3,
    const float* __restrict__ w4, const float* __restrict__ w5,
    __half* __restrict__ WH, __half* __restrict__ WL)
{
    int mat = blockIdx.y;
    const float* ws[6] = {w0, w1, w2, w3, w4, w5};
    const float* w = ws[mat];
    int i = blockIdx.x * 256 + threadIdx.x;
    float v = w[i];
    __half h, l;
    split_f16(v, h, l);
    size_t o = (size_t)mat * DIM * DIM + i;
    WH[o] = h; WL[o] = l;
}

// ============================================================================
// Row sums of E (fp16) -> 1/rho (deterministic tree reduce)
// ============================================================================
__global__ void __launch_bounds__(256) rowsum_inv_kernel(
    const __half* __restrict__ E, float* __restrict__ rhoInv)
{
    size_t row = blockIdx.x;
    const __half2* p = (const __half2*)(E + row * S_LEN);
    int t = threadIdx.x;

    float sum = 0.0f;
    #pragma unroll
    for (int j = 0; j < 8; j++) {
        __half2 v = p[t + j * 256];
        sum += __half2float(v.x) + __half2float(v.y);
    }
    __shared__ float red[8];
    #pragma unroll
    for (int o = 16; o > 0; o >>= 1) sum += __shfl_xor_sync(0xffffffffu, sum, o);
    if ((t & 31) == 0) red[t >> 5] = sum;
    __syncthreads();
    if (t == 0) {
        float tot = red[0] + red[1] + red[2] + red[3] + red[4] + red[5] + red[6] + red[7];
        rhoInv[row] = 1.0f / tot;
    }
}

// ============================================================================
// Final dual LayerNorm (fp32 in/out)
// ============================================================================
__global__ void __launch_bounds__(128) ln_out_kernel(
    const float* __restrict__ x,
    const float* __restrict__ gt, const float* __restrict__ bt,
    const float* __restrict__ gi, const float* __restrict__ bi,
    float* __restrict__ out)
{
    int row = blockIdx.x;
    int srow = row & (ROWS - 1);
    const float *g, *b;
    if (row < ROWS) { g = gt; b = bt; } else { g = gi; b = bi; }
    const float* src = x + (size_t)srow * DIM;

    int t = threadIdx.x;
    float4 v = ((const float4*)src)[t];
    float s  = v.x + v.y + v.z + v.w;
    float ss = v.x*v.x + v.y*v.y + v.z*v.z + v.w*v.w;

    __shared__ float rs[4], rss[4];
    #pragma unroll
    for (int o = 16; o > 0; o >>= 1) {
        s  += __shfl_xor_sync(0xffffffffu, s,  o);
        ss += __shfl_xor_sync(0xffffffffu, ss, o);
    }
    if ((t & 31) == 0) { rs[t>>5] = s; rss[t>>5] = ss; }
    __syncthreads();
    s  = rs[0] + rs[1] + rs[2] + rs[3];
    ss = rss[0] + rss[1] + rss[2] + rss[3];

    float mu  = s * (1.0f / DIM);
    float var = ss * (1.0f / DIM) - mu * mu;
    float inv = rsqrtf(var + 1e-5f);

    float4 gg = ((const float4*)g)[t];
    float4 bb = ((const float4*)b)[t];
    float4 o4;
    o4.x = (v.x - mu) * inv * gg.x + bb.x;
    o4.y = (v.y - mu) * inv * gg.y + bb.y;
    o4.z = (v.z - mu) * inv * gg.z + bb.z;
    o4.w = (v.w - mu) * inv * gg.w + bb.w;
    ((float4*)(out + (size_t)row * DIM))[t] = o4;
}

// ============================================================================
// mma.sync fp16 GEMM (BM=128, BN=64, BK=32, 256 thr, 2 CTA/SM)
// NPASS 3: C = (Ah+Al)@(Bh+Bl) via AhBh+AhBl+AlBh (fp32-grade)
// NPASS 1: C = Ah@Bh (single-pass fp16)
// LAYOUT 0 (NT): B = [N,K] k-contiguous
// LAYOUT 1 (NN): B = [K,N] n-contiguous (ldmatrix.trans)
// EPI 0: fp32 C (alpha + bias)
// EPI 1: fp16 C hi-only (alpha + bias)
// EPI 2: fp16 C = exp(min(alpha*acc, 11))       [scores -> unnorm softmax]
// EPI 3: split fp16 CH/CL = acc * rscale[z*M+m] [PV -> normalized X]
// ============================================================================
template<int LAYOUT, int NPASS, int EPI>
__global__ void __launch_bounds__(THREADS, 2) mma_gemm_kernel(
    const __half* __restrict__ AH, const __half* __restrict__ AL,
    const __half* __restrict__ BH, const __half* __restrict__ BL,
    const float* __restrict__ bias, const float* __restrict__ rscale,
    float* __restrict__ Cf, __half* __restrict__ CH, __half* __restrict__ CL,
    int M, int N, int K, float alpha,
    long long sA, long long sB, long long sC)
{
    constexpr uint32_t ST_AH = 0;
    constexpr uint32_t ST_AL = 8192;
    constexpr uint32_t ST_BH = (NPASS == 1) ? 8192 : 16384;
    constexpr uint32_t ST_BL = 20480;
    constexpr uint32_t STB   = (NPASS == 1) ? 12288 : 24576;

    extern __shared__ char smem[];
    uint32_t base = smem_to_u32(smem);
    int tid = threadIdx.x, wid = tid >> 5, lane = tid & 31;

    int z = blockIdx.z;
    AH += (size_t)z * sA;
    BH += (size_t)z * sB;
    if (NPASS == 3) { AL += (size_t)z * sA; BL += (size_t)z * sB; }

    int m0 = blockIdx.y * BM;
    int n0 = blockIdx.x * BN;
    int NK = K / BK;

    auto load_stage = [&](int kt) {
        uint32_t sb = base + (uint32_t)(kt & (STAGES - 1)) * STB;
        int kb = kt * BK;
        // A: 128 rows x 64B, SW64 swizzle. 512 slots, 2 per thread.
        #pragma unroll
        for (int i = 0; i < 2; i++) {
            int slot = tid + i * THREADS;
            int row = slot >> 2, unit = slot & 3;
            uint32_t off = (uint32_t)(row * 64 + unit * 16);
            off ^= (off >> 3) & 0x30;
            CP_A16(sb + ST_AH + off, AH + (size_t)(m0 + row) * K + kb + unit * 8);
            if (NPASS == 3)
                CP_A16(sb + ST_AL + off, AL + (size_t)(m0 + row) * K + kb + unit * 8);
        }
        if (LAYOUT == 0) {
            // B NT: 64 rows x 64B. 256 slots, 1 per thread.
            int row = tid >> 2, unit = tid & 3;
            uint32_t off = (uint32_t)(row * 64 + unit * 16);
            off ^= (off >> 3) & 0x30;
            CP_A16(sb + ST_BH + off, BH + (size_t)(n0 + row) * K + kb + unit * 8);
            if (NPASS == 3)
                CP_A16(sb + ST_BL + off, BL + (size_t)(n0 + row) * K + kb + unit * 8);
        } else {
            // B NN: 32 k-rows x 128B (BN=64). 256 slots, 1 per thread.
            int row = tid >> 3, unit = tid & 7;
            uint32_t off = (uint32_t)(row * 128 + unit * 16);
            off ^= (off >> 3) & 0x70;
            CP_A16(sb + ST_BH + off, BH + (size_t)(kb + row) * N + n0 + unit * 8);
            if (NPASS == 3)
                CP_A16(sb + ST_BL + off, BL + (size_t)(kb + row) * N + n0 + unit * 8);
        }
    };

    load_stage(0); CP_COMMIT();
    load_stage(1); CP_COMMIT();
    load_stage(2); CP_COMMIT();

    int wm = wid & 3, wn = wid >> 2;     // 4x2 warp grid, 32x32 warp tile
    float acc[2][4][4];
    #pragma unroll
    for (int a = 0; a < 2; a++)
        #pragma unroll
        for (int b = 0; b < 4; b++)
            #pragma unroll
            for (int c = 0; c < 4; c++) acc[a][b][c] = 0.0f;

    for (int kt = 0; kt < NK; kt++) {
        if (kt + 3 < NK)      { load_stage(kt + 3); CP_COMMIT(); CP_WAIT(3); }
        else if (kt + 2 < NK) { CP_WAIT(2); }
        else if (kt + 1 < NK) { CP_WAIT(1); }
        else                  { CP_WAIT(0); }
        __syncthreads();

        uint32_t sb = base + (uint32_t)(kt & (STAGES - 1)) * STB;

        #pragma unroll
        for (int ks = 0; ks < 2; ks++) {
            int k0 = ks * 16;

            uint32_t ah[2][4], al[2][4];
            #pragma unroll
            for (int mt = 0; mt < 2; mt++) {
                int row = wm * 32 + mt * 16 + (lane & 15);
                uint32_t off = (uint32_t)(row * 64 + k0 * 2 + ((lane >> 4) << 4));
                off ^= (off >> 3) & 0x30;
                ldm_x4(ah[mt], sb + ST_AH + off);
                if (NPASS == 3) ldm_x4(al[mt], sb + ST_AL + off);
            }

            uint32_t bh[4][2], bl[4][2];
            if (LAYOUT == 0) {
                #pragma unroll
                for (int p = 0; p < 2; p++) {
                    int nrow = wn * 32 + p * 16 + (lane & 7) + 8 * ((lane >> 4) & 1);
                    uint32_t off = (uint32_t)(nrow * 64 + k0 * 2 + ((lane >> 3) & 1) * 16);
                    off ^= (off >> 3) & 0x30;
                    uint32_t r[4];
                    ldm_x4(r, sb + ST_BH + off);
                    bh[p*2][0] = r[0]; bh[p*2][1] = r[1];
                    bh[p*2+1][0] = r[2]; bh[p*2+1][1] = r[3];
                    if (NPASS == 3) {
                        ldm_x4(r, sb + ST_BL + off);
                        bl[p*2][0] = r[0]; bl[p*2][1] = r[1];
                        bl[p*2+1][0] = r[2]; bl[p*2+1][1] = r[3];
                    }
                }
            } else {
                #pragma unroll
                for (int p = 0; p < 2; p++) {
                    int krow = k0 + (lane & 7) + 8 * ((lane >> 3) & 1);
                    int ncol = wn * 32 + p * 16 + 8 * (lane >> 4);
                    uint32_t off = (uint32_t)(krow * 128 + ncol * 2);
                    off ^= (off >> 3) & 0x70;
                    uint32_t r[4];
                    ldm_x4_t(r, sb + ST_BH + off);
                    bh[p*2][0] = r[0]; bh[p*2][1] = r[1];
                    bh[p*2+1][0] = r[2]; bh[p*2+1][1] = r[3];
                    if (NPASS == 3) {
                        ldm_x4_t(r, sb + ST_BL + off);
                        bl[p*2][0] = r[0]; bl[p*2][1] = r[1];
                        bl[p*2+1][0] = r[2]; bl[p*2+1][1] = r[3];
                    }
                }
            }

            #pragma unroll
            for (int mt = 0; mt < 2; mt++)
                #pragma unroll
                for (int nt = 0; nt < 4; nt++) {
                    mma_f16(acc[mt][nt], ah[mt], bh[nt]);
                    if (NPASS == 3) {
                        mma_f16(acc[mt][nt], ah[mt], bl[nt]);
                        mma_f16(acc[mt][nt], al[mt], bh[nt]);
                    }
                }
        }
        __syncthreads();
    }

    // ---------------- epilogue ----------------
    #pragma unroll
    for (int mt = 0; mt < 2; mt++) {
        int mrow = m0 + wm * 32 + mt * 16 + (lane >> 2);
        float rs0 = 1.0f, rs1 = 1.0f;
        if (EPI == 3) {
            rs0 = __ldg(&rscale[(size_t)z * M + mrow]);
            rs1 = __ldg(&rscale[(size_t)z * M + mrow + 8]);
        }
        #pragma unroll
        for (int nt = 0; nt < 4; nt++) {
            int m = mrow;
            int n = n0 + wn * 32 + nt * 8 + (lane & 3) * 2;
            float c0, c1, c2, c3;
            if (EPI == 0 || EPI == 1) {
                float b0 = bias ? __ldg(&bias[n])     : 0.0f;
                float b1 = bias ? __ldg(&bias[n + 1]) : 0.0f;
                c0 = alpha * acc[mt][nt][0] + b0;
                c1 = alpha * acc[mt][nt][1] + b1;
                c2 = alpha * acc[mt][nt][2] + b0;
                c3 = alpha * acc[mt][nt][3] + b1;
            } else if (EPI == 2) {
                c0 = __expf(fminf(alpha * acc[mt][nt][0], 11.0f));
                c1 = __expf(fminf(alpha * acc[mt][nt][1], 11.0f));
                c2 = __expf(fminf(alpha * acc[mt][nt][2], 11.0f));
                c3 = __expf(fminf(alpha * acc[mt][nt][3], 11.0f));
            } else {  // EPI == 3
                c0 = acc[mt][nt][0] * rs0;
                c1 = acc[mt][nt][1] * rs0;
                c2 = acc[mt][nt][2] * rs1;
                c3 = acc[mt][nt][3] * rs1;
            }
            size_t o0 = (size_t)z * sC + (size_t)m * N + n;
            size_t o1 = (size_t)z * sC + (size_t)(m + 8) * N + n;
            if (EPI == 0) {
                *(float2*)(Cf + o0) = make_float2(c0, c1);
                *(float2*)(Cf + o1) = make_float2(c2, c3);
            } else if (EPI == 1 || EPI == 2) {
                *(__half2*)(CH + o0) = __halves2half2(__float2half(c0), __float2half(c1));
                *(__half2*)(CH + o1) = __halves2half2(__float2half(c2), __float2half(c3));
            } else {
                __half h0,l0,h1,l1,h2,l2,h3,l3;
                split_f16(c0,h0,l0); split_f16(c1,h1,l1);
                split_f16(c2,h2,l2); split_f16(c3,h3,l3);
                *(__half2*)(CH + o0) = __halves2half2(h0, h1);
                *(__half2*)(CL + o0) = __halves2half2(l0, l1);
                *(__half2*)(CH + o1) = __halves2half2(h2, h3);
                *(__half2*)(CL + o1) = __halves2half2(l2, l3);
            }
        }
    }
}

// ============================================================================
// Host orchestration
// ============================================================================
extern "C" void kernel_launch(void* const* d_in, const int* in_sizes, int n_in,
                              void* d_out, int out_size)
{
    const float* text  = (const float*)d_in[0];
    const float* img   = (const float*)d_in[1];
    const float* ln_tg = (const float*)d_in[2];
    const float* ln_tb = (const float*)d_in[3];
    const float* ln_ig = (const float*)d_in[4];
    const float* ln_ib = (const float*)d_in[5];
    const float* Wq  = (const float*)d_in[6];  const float* bq  = (const float*)d_in[7];
    const float* Wkt = (const float*)d_in[8];  const float* bkt = (const float*)d_in[9];
    const float* Wvt = (const float*)d_in[10]; const float* bvt = (const float*)d_in[11];
    const float* Wki = (const float*)d_in[12]; const float* bki = (const float*)d_in[13];
    const float* Wvi = (const float*)d_in[14]; const float* bvi = (const float*)d_in[15];
    const float* Wo  = (const float*)d_in[16]; const float* bo  = (const float*)d_in[17];
    float* out = (float*)d_out;

    static bool attr_done = false;
    if (!attr_done) {
        cudaFuncSetAttribute(mma_gemm_kernel<0,3,1>, cudaFuncAttributeMaxDynamicSharedMemorySize, SMEM_N3);
        cudaFuncSetAttribute(mma_gemm_kernel<0,3,0>, cudaFuncAttributeMaxDynamicSharedMemorySize, SMEM_N3);
        cudaFuncSetAttribute(mma_gemm_kernel<0,1,2>, cudaFuncAttributeMaxDynamicSharedMemorySize, SMEM_N1);
        cudaFuncSetAttribute(mma_gemm_kernel<1,1,3>, cudaFuncAttributeMaxDynamicSharedMemorySize, SMEM_N1);
        attr_done = true;
    }

    void *pNH, *pNL, *pQ, *pK, *pV, *pE, *pXH, *pXL, *pWH, *pWL, *pRI, *pXO;
    cudaGetSymbolAddress(&pNH, g_normsH); cudaGetSymbolAddress(&pNL, g_normsL);
    cudaGetSymbolAddress(&pQ, g_Q); cudaGetSymbolAddress(&pK, g_K); cudaGetSymbolAddress(&pV, g_V);
    cudaGetSymbolAddress(&pE, g_E);
    cudaGetSymbolAddress(&pXH, g_XH); cudaGetSymbolAddress(&pXL, g_XL);
    cudaGetSymbolAddress(&pWH, g_WH); cudaGetSymbolAddress(&pWL, g_WL);
    cudaGetSymbolAddress(&pRI, g_rhoInv); cudaGetSymbolAddress(&pXO, g_XO);

    __half* NH = (__half*)pNH; __half* NL = (__half*)pNL;
    __half* Q  = (__half*)pQ;  __half* K  = (__half*)pK;  __half* V = (__half*)pV;
    __half* E  = (__half*)pE;
    __half* XH = (__half*)pXH; __half* XL = (__half*)pXL;
    __half* WH = (__half*)pWH; __half* WL = (__half*)pWL;
    float* RI = (float*)pRI;
    float* XO = (float*)pXO;

    const float scale = 0.04419417382415922f;  // 512^-0.5
    const int HALF = 2 * S_LEN;                // 8192 rows per modality
    const size_t WSZ = (size_t)DIM * DIM;      // 262144

    // 1) input LN + split
    ln_in_split_kernel<<<ROWS, 128>>>(text, img, ln_tg, ln_tb, ln_ig, ln_ib, NH, NL);

    // 2) split weights (order: q, kt, vt, ki, vi, o)
    split_weights_kernel<<<dim3(1024, 6), 256>>>(Wq, Wkt, Wvt, Wki, Wvi, Wo, WH, WL);

    // 3) projections (NT, 3-pass, fp16 hi-only out)
    mma_gemm_kernel<0,3,1><<<dim3(8, 128, 1), THREADS, SMEM_N3>>>(
        NH, NL, WH + 0*WSZ, WL + 0*WSZ, bq, nullptr, nullptr, Q, nullptr,
        ROWS, DIM, DIM, 1.0f, 0, 0, 0);
    mma_gemm_kernel<0,3,1><<<dim3(8, 64, 1), THREADS, SMEM_N3>>>(
        NH, NL, WH + 1*WSZ, WL + 1*WSZ, bkt, nullptr, nullptr, K, nullptr,
        HALF, DIM, DIM, 1.0f, 0, 0, 0);
    mma_gemm_kernel<0,3,1><<<dim3(8, 64, 1), THREADS, SMEM_N3>>>(
        NH + (size_t)HALF * DIM, NL + (size_t)HALF * DIM,
        WH + 3*WSZ, WL + 3*WSZ, bki, nullptr, nullptr,
        K + (size_t)HALF * DIM, nullptr,
        HALF, DIM, DIM, 1.0f, 0, 0, 0);
    mma_gemm_kernel<0,3,1><<<dim3(8, 64, 1), THREADS, SMEM_N3>>>(
        NH, NL, WH + 2*WSZ, WL + 2*WSZ, bvt, nullptr, nullptr, V, nullptr,
        HALF, DIM, DIM, 1.0f, 0, 0, 0);
    mma_gemm_kernel<0,3,1><<<dim3(8, 64, 1), THREADS, SMEM_N3>>>(
        NH + (size_t)HALF * DIM, NL + (size_t)HALF * DIM,
        WH + 4*WSZ, WL + 4*WSZ, bvi, nullptr, nullptr,
        V + (size_t)HALF * DIM, nullptr,
        HALF, DIM, DIM, 1.0f, 0, 0, 0);

    // 4) E = exp(scale * Q @ K^T) (batched NT, single-pass fp16)
    mma_gemm_kernel<0,1,2><<<dim3(64, 32, NBAT), THREADS, SMEM_N1>>>(
        Q, nullptr, K, nullptr, nullptr, nullptr, nullptr, E, nullptr,
        S_LEN, S_LEN, DIM, scale,
        (long long)S_LEN * DIM, (long long)S_LEN * DIM, (long long)S_LEN * S_LEN);

    // 5) rho^-1 = 1 / rowsum(E)
    rowsum_inv_kernel<<<ROWS, 256>>>(E, RI);

    // 6) X = (E @ V) * rho^-1 (batched NN, single-pass fp16, split out)
    mma_gemm_kernel<1,1,3><<<dim3(8, 32, NBAT), THREADS, SMEM_N1>>>(
        E, nullptr, V, nullptr, nullptr, RI, nullptr, XH, XL,
        S_LEN, DIM, S_LEN, 1.0f,
        (long long)S_LEN * S_LEN, (long long)S_LEN * DIM, (long long)S_LEN * DIM);

    // 7) XO = X @ Wo^T + bo (NT, 3-pass, fp32 out)
    mma_gemm_kernel<0,3,0><<<dim3(8, 128, 1), THREADS, SMEM_N3>>>(
        XH, XL, WH + 5*WSZ, WL + 5*WSZ, bo, nullptr, XO, nullptr, nullptr,
        ROWS, DIM, DIM, 1.0f, 0, 0, 0);

    // 8) final dual LayerNorm
    ln_out_kernel<<<2 * ROWS, 128>>>(XO, ln_tg, ln_tb, ln_ig, ln_ib, out);
}

// round 11
// speedup vs baseline: 6.7046x; 1.2597x over previous
#include <cuda_runtime.h>
#include <cuda_fp16.h>
#include <cstdint>
#include <math.h>

// ============================================================================
// Problem constants
// ============================================================================
#define DIM   512
#define S_LEN 4096
#define NBAT  4
#define ROWS  (NBAT * S_LEN)      // 16384

// GEMM tiling: BM=128, BN=64, BK=32, 256 threads (8 warps, 4x2 grid, 32x32 warp tile)
#define BM 128
#define BN 64
#define BK 32
#define THREADS 256
#define STAGES 4
// stage layout: A 8KB | B 4KB = 12KB
#define ST_A 0
#define ST_B 8192
#define STB  12288
#define SMEM_DYN (STAGES * STB)   // 49152

// ============================================================================
// PTX helpers (plain sm_103-legal: cp.async / ldmatrix / mma.sync only)
// ============================================================================
__device__ __forceinline__ uint32_t smem_to_u32(const void* p) {
    uint32_t a;
    asm("{ .reg .u64 t; cvta.to.shared.u64 t, %1; cvt.u32.u64 %0, t; }" : "=r"(a) : "l"(p));
    return a;
}
#define CP_A16(s, g) \
    asm volatile("cp.async.cg.shared.global [%0], [%1], 16;" :: "r"(s), "l"(g))
#define CP_COMMIT() asm volatile("cp.async.commit_group;" ::: "memory")
#define CP_WAIT(n)  asm volatile("cp.async.wait_group %0;" :: "n"(n) : "memory")

__device__ __forceinline__ void ldm_x4(uint32_t* r, uint32_t addr) {
    asm volatile("ldmatrix.sync.aligned.m8n8.x4.shared.b16 {%0,%1,%2,%3}, [%4];"
        : "=r"(r[0]), "=r"(r[1]), "=r"(r[2]), "=r"(r[3]) : "r"(addr));
}
__device__ __forceinline__ void ldm_x4_t(uint32_t* r, uint32_t addr) {
    asm volatile("ldmatrix.sync.aligned.m8n8.x4.trans.shared.b16 {%0,%1,%2,%3}, [%4];"
        : "=r"(r[0]), "=r"(r[1]), "=r"(r[2]), "=r"(r[3]) : "r"(addr));
}
__device__ __forceinline__ void mma_f16(float* d, const uint32_t* a, const uint32_t* b) {
    asm volatile("mma.sync.aligned.m16n8k16.row.col.f32.f16.f16.f32 "
        "{%0,%1,%2,%3}, {%4,%5,%6,%7}, {%8,%9}, {%0,%1,%2,%3};"
        : "+f"(d[0]), "+f"(d[1]), "+f"(d[2]), "+f"(d[3])
        : "r"(a[0]), "r"(a[1]), "r"(a[2]), "r"(a[3]), "r"(b[0]), "r"(b[1]));
}

// ============================================================================
// Scratch buffers
// ============================================================================
__device__ __align__(128) __half g_norms[(size_t)ROWS * DIM];
__device__ __align__(128) __half g_Q[(size_t)ROWS * DIM];
__device__ __align__(128) __half g_K[(size_t)ROWS * DIM];
__device__ __align__(128) __half g_V[(size_t)ROWS * DIM];
__device__ __align__(128) __half g_E[(size_t)NBAT * S_LEN * S_LEN];   // exp(scores), fp16
__device__ __align__(128) __half g_X[(size_t)ROWS * DIM];
__device__ __align__(128) __half g_W[(size_t)6 * DIM * DIM];
__device__ __align__(128) float g_Spart[(size_t)NBAT * S_LEN * 64];   // per-nblock row sums
__device__ __align__(128) float g_rhoInv[(size_t)ROWS];
__device__ __align__(128) float g_XO[(size_t)ROWS * DIM];

// ============================================================================
// Input LayerNorm -> fp16 norms
// ============================================================================
__global__ void __launch_bounds__(128) ln_in_kernel(
    const float* __restrict__ text, const float* __restrict__ img,
    const float* __restrict__ gt, const float* __restrict__ bt,
    const float* __restrict__ gi, const float* __restrict__ bi,
    __half* __restrict__ outH)
{
    int row = blockIdx.x;
    const float *src, *g, *b;
    if (row < 2 * S_LEN) { src = text + (size_t)row * DIM;              g = gt; b = bt; }
    else                 { src = img  + (size_t)(row - 2*S_LEN) * DIM;  g = gi; b = bi; }

    int t = threadIdx.x;
    float4 x = ((const float4*)src)[t];
    float s  = x.x + x.y + x.z + x.w;
    float ss = x.x*x.x + x.y*x.y + x.z*x.z + x.w*x.w;

    __shared__ float rs[4], rss[4];
    #pragma unroll
    for (int o = 16; o > 0; o >>= 1) {
        s  += __shfl_xor_sync(0xffffffffu, s,  o);
        ss += __shfl_xor_sync(0xffffffffu, ss, o);
    }
    if ((t & 31) == 0) { rs[t>>5] = s; rss[t>>5] = ss; }
    __syncthreads();
    s  = rs[0] + rs[1] + rs[2] + rs[3];
    ss = rss[0] + rss[1] + rss[2] + rss[3];

    float mu  = s * (1.0f / DIM);
    float var = ss * (1.0f / DIM) - mu * mu;
    float inv = rsqrtf(var + 1e-5f);

    float4 gg = ((const float4*)g)[t];
    float4 bb = ((const float4*)b)[t];
    float v0 = (x.x - mu) * inv * gg.x + bb.x;
    float v1 = (x.y - mu) * inv * gg.y + bb.y;
    float v2 = (x.z - mu) * inv * gg.z + bb.z;
    float v3 = (x.w - mu) * inv * gg.w + bb.w;

    size_t base = (size_t)row * DIM + t * 4;
    ((__half2*)(outH + base))[0] = __halves2half2(__float2half(v0), __float2half(v1));
    ((__half2*)(outH + base))[1] = __halves2half2(__float2half(v2), __float2half(v3));
}

// ============================================================================
// Convert 6 weight matrices to fp16
// ============================================================================
__global__ void __launch_bounds__(256) convert_weights_kernel(
    const float* __restrict__ w0, const float* __restrict__ w1,
    const float* __restrict__ w2, const float* __restrict__ w3,
    const float* __restrict__ w4, const float* __restrict__ w5,
    __half* __restrict__ W)
{
    int mat = blockIdx.y;
    const float* ws[6] = {w0, w1, w2, w3, w4, w5};
    const float* w = ws[mat];
    int i = blockIdx.x * 256 + threadIdx.x;
    W[(size_t)mat * DIM * DIM + i] = __float2half(w[i]);
}

// ============================================================================
// Reduce 64 per-nblock partial sums per row -> 1/rho. 8 warps = 8 rows/block.
// ============================================================================
__global__ void __launch_bounds__(256) rho_reduce_kernel(
    const float* __restrict__ part, float* __restrict__ rhoInv)
{
    int tid = threadIdx.x;
    int row = blockIdx.x * 8 + (tid >> 5);
    int lane = tid & 31;
    const float* p = part + (size_t)row * 64;
    float s = p[lane] + p[lane + 32];
    #pragma unroll
    for (int o = 16; o > 0; o >>= 1) s += __shfl_xor_sync(0xffffffffu, s, o);
    if (lane == 0) rhoInv[row] = 1.0f / s;
}

// ============================================================================
// Final dual LayerNorm (fp32 in/out)
// ============================================================================
__global__ void __launch_bounds__(128) ln_out_kernel(
    const float* __restrict__ x,
    const float* __restrict__ gt, const float* __restrict__ bt,
    const float* __restrict__ gi, const float* __restrict__ bi,
    float* __restrict__ out)
{
    int row = blockIdx.x;
    int srow = row & (ROWS - 1);
    const float *g, *b;
    if (row < ROWS) { g = gt; b = bt; } else { g = gi; b = bi; }
    const float* src = x + (size_t)srow * DIM;

    int t = threadIdx.x;
    float4 v = ((const float4*)src)[t];
    float s  = v.x + v.y + v.z + v.w;
    float ss = v.x*v.x + v.y*v.y + v.z*v.z + v.w*v.w;

    __shared__ float rs[4], rss[4];
    #pragma unroll
    for (int o = 16; o > 0; o >>= 1) {
        s  += __shfl_xor_sync(0xffffffffu, s,  o);
        ss += __shfl_xor_sync(0xffffffffu, ss, o);
    }
    if ((t & 31) == 0) { rs[t>>5] = s; rss[t>>5] = ss; }
    __syncthreads();
    s  = rs[0] + rs[1] + rs[2] + rs[3];
    ss = rss[0] + rss[1] + rss[2] + rss[3];

    float mu  = s * (1.0f / DIM);
    float var = ss * (1.0f / DIM) - mu * mu;
    float inv = rsqrtf(var + 1e-5f);

    float4 gg = ((const float4*)g)[t];
    float4 bb = ((const float4*)b)[t];
    float4 o4;
    o4.x = (v.x - mu) * inv * gg.x + bb.x;
    o4.y = (v.y - mu) * inv * gg.y + bb.y;
    o4.z = (v.z - mu) * inv * gg.z + bb.z;
    o4.w = (v.w - mu) * inv * gg.w + bb.w;
    ((float4*)(out + (size_t)row * DIM))[t] = o4;
}

// ============================================================================
// mma.sync fp16 single-pass GEMM (BM=128, BN=64, BK=32, 256 thr, 2 CTA/SM)
// LAYOUT 0 (NT): B = [N,K] k-contiguous
// LAYOUT 1 (NN): B = [K,N] n-contiguous (ldmatrix.trans)
// EPI 0: fp32 C (alpha + bias)                           [Wo -> XO]
// EPI 1: fp16 C (alpha + bias)                           [projections]
// EPI 2: fp16 C = exp(min(alpha*acc,11)) + row partials  [scores -> E, Spart]
// EPI 3: fp16 C = acc * rscale[z*M+m]                    [PV -> X]
// ============================================================================
template<int LAYOUT, int EPI>
__global__ void __launch_bounds__(THREADS, 2) mma_gemm_kernel(
    const __half* __restrict__ A, const __half* __restrict__ B,
    const float* __restrict__ bias, const float* __restrict__ rscale,
    float* __restrict__ Cf, __half* __restrict__ CH, float* __restrict__ Spart,
    int M, int N, int K, float alpha,
    long long sA, long long sB, long long sC)
{
    extern __shared__ char smem[];
    uint32_t base = smem_to_u32(smem);
    int tid = threadIdx.x, wid = tid >> 5, lane = tid & 31;

    int z = blockIdx.z;
    A += (size_t)z * sA;
    B += (size_t)z * sB;

    int m0 = blockIdx.y * BM;
    int n0 = blockIdx.x * BN;
    int NK = K / BK;

    auto load_stage = [&](int kt) {
        uint32_t sb = base + (uint32_t)(kt & (STAGES - 1)) * STB;
        int kb = kt * BK;
        // A: 128 rows x 64B, SW64 swizzle. 512 slots, 2 per thread.
        #pragma unroll
        for (int i = 0; i < 2; i++) {
            int slot = tid + i * THREADS;
            int row = slot >> 2, unit = slot & 3;
            uint32_t off = (uint32_t)(row * 64 + unit * 16);
            off ^= (off >> 3) & 0x30;
            CP_A16(sb + ST_A + off, A + (size_t)(m0 + row) * K + kb + unit * 8);
        }
        if (LAYOUT == 0) {
            // B NT: 64 rows x 64B. 256 slots, 1 per thread.
            int row = tid >> 2, unit = tid & 3;
            uint32_t off = (uint32_t)(row * 64 + unit * 16);
            off ^= (off >> 3) & 0x30;
            CP_A16(sb + ST_B + off, B + (size_t)(n0 + row) * K + kb + unit * 8);
        } else {
            // B NN: 32 k-rows x 128B (BN=64). 256 slots, 1 per thread.
            int row = tid >> 3, unit = tid & 7;
            uint32_t off = (uint32_t)(row * 128 + unit * 16);
            off ^= (off >> 3) & 0x70;
            CP_A16(sb + ST_B + off, B + (size_t)(kb + row) * N + n0 + unit * 8);
        }
    };

    load_stage(0); CP_COMMIT();
    load_stage(1); CP_COMMIT();
    load_stage(2); CP_COMMIT();

    int wm = wid & 3, wn = wid >> 2;     // 4x2 warp grid, 32x32 warp tile
    float acc[2][4][4];
    #pragma unroll
    for (int a = 0; a < 2; a++)
        #pragma unroll
        for (int b = 0; b < 4; b++)
            #pragma unroll
            for (int c = 0; c < 4; c++) acc[a][b][c] = 0.0f;

    for (int kt = 0; kt < NK; kt++) {
        if (kt + 3 < NK)      { load_stage(kt + 3); CP_COMMIT(); CP_WAIT(3); }
        else if (kt + 2 < NK) { CP_WAIT(2); }
        else if (kt + 1 < NK) { CP_WAIT(1); }
        else                  { CP_WAIT(0); }
        __syncthreads();

        uint32_t sb = base + (uint32_t)(kt & (STAGES - 1)) * STB;

        #pragma unroll
        for (int ks = 0; ks < 2; ks++) {
            int k0 = ks * 16;

            uint32_t ar[2][4];
            #pragma unroll
            for (int mt = 0; mt < 2; mt++) {
                int row = wm * 32 + mt * 16 + (lane & 15);
                uint32_t off = (uint32_t)(row * 64 + k0 * 2 + ((lane >> 4) << 4));
                off ^= (off >> 3) & 0x30;
                ldm_x4(ar[mt], sb + ST_A + off);
            }

            uint32_t br[4][2];
            if (LAYOUT == 0) {
                #pragma unroll
                for (int p = 0; p < 2; p++) {
                    int nrow = wn * 32 + p * 16 + (lane & 7) + 8 * ((lane >> 4) & 1);
                    uint32_t off = (uint32_t)(nrow * 64 + k0 * 2 + ((lane >> 3) & 1) * 16);
                    off ^= (off >> 3) & 0x30;
                    uint32_t r[4];
                    ldm_x4(r, sb + ST_B + off);
                    br[p*2][0] = r[0]; br[p*2][1] = r[1];
                    br[p*2+1][0] = r[2]; br[p*2+1][1] = r[3];
                }
            } else {
                #pragma unroll
                for (int p = 0; p < 2; p++) {
                    int krow = k0 + (lane & 7) + 8 * ((lane >> 3) & 1);
                    int ncol = wn * 32 + p * 16 + 8 * (lane >> 4);
                    uint32_t off = (uint32_t)(krow * 128 + ncol * 2);
                    off ^= (off >> 3) & 0x70;
                    uint32_t r[4];
                    ldm_x4_t(r, sb + ST_B + off);
                    br[p*2][0] = r[0]; br[p*2][1] = r[1];
                    br[p*2+1][0] = r[2]; br[p*2+1][1] = r[3];
                }
            }

            #pragma unroll
            for (int mt = 0; mt < 2; mt++)
                #pragma unroll
                for (int nt = 0; nt < 4; nt++)
                    mma_f16(acc[mt][nt], ar[mt], br[nt]);
        }
        __syncthreads();
    }

    // ---------------- epilogue ----------------
    float psum[2][2] = {{0.0f, 0.0f}, {0.0f, 0.0f}};   // [mt][row m / m+8]

    #pragma unroll
    for (int mt = 0; mt < 2; mt++) {
        int mrow = m0 + wm * 32 + mt * 16 + (lane >> 2);
        float rs0 = 1.0f, rs1 = 1.0f;
        if (EPI == 3) {
            rs0 = __ldg(&rscale[(size_t)z * M + mrow]);
            rs1 = __ldg(&rscale[(size_t)z * M + mrow + 8]);
        }
        #pragma unroll
        for (int nt = 0; nt < 4; nt++) {
            int n = n0 + wn * 32 + nt * 8 + (lane & 3) * 2;
            float c0, c1, c2, c3;
            if (EPI == 0 || EPI == 1) {
                float b0 = bias ? __ldg(&bias[n])     : 0.0f;
                float b1 = bias ? __ldg(&bias[n + 1]) : 0.0f;
                c0 = alpha * acc[mt][nt][0] + b0;
                c1 = alpha * acc[mt][nt][1] + b1;
                c2 = alpha * acc[mt][nt][2] + b0;
                c3 = alpha * acc[mt][nt][3] + b1;
            } else if (EPI == 2) {
                c0 = __expf(fminf(alpha * acc[mt][nt][0], 11.0f));
                c1 = __expf(fminf(alpha * acc[mt][nt][1], 11.0f));
                c2 = __expf(fminf(alpha * acc[mt][nt][2], 11.0f));
                c3 = __expf(fminf(alpha * acc[mt][nt][3], 11.0f));
                psum[mt][0] += c0 + c1;
                psum[mt][1] += c2 + c3;
            } else {  // EPI == 3
                c0 = acc[mt][nt][0] * rs0;
                c1 = acc[mt][nt][1] * rs0;
                c2 = acc[mt][nt][2] * rs1;
                c3 = acc[mt][nt][3] * rs1;
            }
            size_t o0 = (size_t)z * sC + (size_t)mrow * N + n;
            size_t o1 = (size_t)z * sC + (size_t)(mrow + 8) * N + n;
            if (EPI == 0) {
                *(float2*)(Cf + o0) = make_float2(c0, c1);
                *(float2*)(Cf + o1) = make_float2(c2, c3);
            } else {
                *(__half2*)(CH + o0) = __halves2half2(__float2half(c0), __float2half(c1));
                *(__half2*)(CH + o1) = __halves2half2(__float2half(c2), __float2half(c3));
            }
        }
    }

    if (EPI == 2) {
        // deterministic row-sum reduction: lane&3 via shfl, wn via smem.
        #pragma unroll
        for (int mt = 0; mt < 2; mt++)
            #pragma unroll
            for (int j = 0; j < 2; j++) {
                psum[mt][j] += __shfl_xor_sync(0xffffffffu, psum[mt][j], 1);
                psum[mt][j] += __shfl_xor_sync(0xffffffffu, psum[mt][j], 2);
            }
        float* red = (float*)smem;   // [2][128], reuses pipeline smem
        if ((lane & 3) == 0) {
            #pragma unroll
            for (int mt = 0; mt < 2; mt++) {
                int lr = wm * 32 + mt * 16 + (lane >> 2);
                red[wn * 128 + lr]     = psum[mt][0];
                red[wn * 128 + lr + 8] = psum[mt][1];
            }
        }
        __syncthreads();
        if (tid < 128) {
            Spart[((size_t)z * S_LEN + m0 + tid) * 64 + blockIdx.x] =
                red[tid] + red[128 + tid];
        }
    }
}

// ============================================================================
// Host orchestration
// ============================================================================
extern "C" void kernel_launch(void* const* d_in, const int* in_sizes, int n_in,
                              void* d_out, int out_size)
{
    const float* text  = (const float*)d_in[0];
    const float* img   = (const float*)d_in[1];
    const float* ln_tg = (const float*)d_in[2];
    const float* ln_tb = (const float*)d_in[3];
    const float* ln_ig = (const float*)d_in[4];
    const float* ln_ib = (const float*)d_in[5];
    const float* Wq  = (const float*)d_in[6];  const float* bq  = (const float*)d_in[7];
    const float* Wkt = (const float*)d_in[8];  const float* bkt = (const float*)d_in[9];
    const float* Wvt = (const float*)d_in[10]; const float* bvt = (const float*)d_in[11];
    const float* Wki = (const float*)d_in[12]; const float* bki = (const float*)d_in[13];
    const float* Wvi = (const float*)d_in[14]; const float* bvi = (const float*)d_in[15];
    const float* Wo  = (const float*)d_in[16]; const float* bo  = (const float*)d_in[17];
    float* out = (float*)d_out;

    static bool attr_done = false;
    if (!attr_done) {
        cudaFuncSetAttribute(mma_gemm_kernel<0,0>, cudaFuncAttributeMaxDynamicSharedMemorySize, SMEM_DYN);
        cudaFuncSetAttribute(mma_gemm_kernel<0,1>, cudaFuncAttributeMaxDynamicSharedMemorySize, SMEM_DYN);
        cudaFuncSetAttribute(mma_gemm_kernel<0,2>, cudaFuncAttributeMaxDynamicSharedMemorySize, SMEM_DYN);
        cudaFuncSetAttribute(mma_gemm_kernel<1,3>, cudaFuncAttributeMaxDynamicSharedMemorySize, SMEM_DYN);
        attr_done = true;
    }

    void *pN, *pQ, *pK, *pV, *pE, *pX, *pW, *pSP, *pRI, *pXO;
    cudaGetSymbolAddress(&pN, g_norms);
    cudaGetSymbolAddress(&pQ, g_Q); cudaGetSymbolAddress(&pK, g_K); cudaGetSymbolAddress(&pV, g_V);
    cudaGetSymbolAddress(&pE, g_E); cudaGetSymbolAddress(&pX, g_X);
    cudaGetSymbolAddress(&pW, g_W); cudaGetSymbolAddress(&pSP, g_Spart);
    cudaGetSymbolAddress(&pRI, g_rhoInv); cudaGetSymbolAddress(&pXO, g_XO);

    __half* NORM = (__half*)pN;
    __half* Q = (__half*)pQ; __half* K = (__half*)pK; __half* V = (__half*)pV;
    __half* E = (__half*)pE; __half* X = (__half*)pX;
    __half* W = (__half*)pW;
    float* SP = (float*)pSP;
    float* RI = (float*)pRI;
    float* XO = (float*)pXO;

    const float scale = 0.04419417382415922f;  // 512^-0.5
    const int HALF = 2 * S_LEN;                // 8192 rows per modality
    const size_t WSZ = (size_t)DIM * DIM;      // 262144

    // 1) input LN -> fp16 norms
    ln_in_kernel<<<ROWS, 128>>>(text, img, ln_tg, ln_tb, ln_ig, ln_ib, NORM);

    // 2) convert weights (order: q, kt, vt, ki, vi, o)
    convert_weights_kernel<<<dim3(1024, 6), 256>>>(Wq, Wkt, Wvt, Wki, Wvi, Wo, W);

    // 3) projections (NT, single-pass fp16)
    mma_gemm_kernel<0,1><<<dim3(8, 128, 1), THREADS, SMEM_DYN>>>(
        NORM, W + 0*WSZ, bq, nullptr, nullptr, Q, nullptr,
        ROWS, DIM, DIM, 1.0f, 0, 0, 0);
    mma_gemm_kernel<0,1><<<dim3(8, 64, 1), THREADS, SMEM_DYN>>>(
        NORM, W + 1*WSZ, bkt, nullptr, nullptr, K, nullptr,
        HALF, DIM, DIM, 1.0f, 0, 0, 0);
    mma_gemm_kernel<0,1><<<dim3(8, 64, 1), THREADS, SMEM_DYN>>>(
        NORM + (size_t)HALF * DIM, W + 3*WSZ, bki, nullptr, nullptr,
        K + (size_t)HALF * DIM,
        nullptr, HALF, DIM, DIM, 1.0f, 0, 0, 0);
    mma_gemm_kernel<0,1><<<dim3(8, 64, 1), THREADS, SMEM_DYN>>>(
        NORM, W + 2*WSZ, bvt, nullptr, nullptr, V, nullptr,
        HALF, DIM, DIM, 1.0f, 0, 0, 0);
    mma_gemm_kernel<0,1><<<dim3(8, 64, 1), THREADS, SMEM_DYN>>>(
        NORM + (size_t)HALF * DIM, W + 4*WSZ, bvi, nullptr, nullptr,
        V + (size_t)HALF * DIM,
        nullptr, HALF, DIM, DIM, 1.0f, 0, 0, 0);

    // 4) E = exp(scale * Q @ K^T), with fused per-nblock row sums
    mma_gemm_kernel<0,2><<<dim3(64, 32, NBAT), THREADS, SMEM_DYN>>>(
        Q, K, nullptr, nullptr, nullptr, E, SP,
        S_LEN, S_LEN, DIM, scale,
        (long long)S_LEN * DIM, (long long)S_LEN * DIM, (long long)S_LEN * S_LEN);

    // 5) rho^-1 from partials (4 MB read)
    rho_reduce_kernel<<<ROWS / 8, 256>>>(SP, RI);

    // 6) X = (E @ V) * rho^-1 (batched NN, single-pass fp16)
    mma_gemm_kernel<1,3><<<dim3(8, 32, NBAT), THREADS, SMEM_DYN>>>(
        E, V, nullptr, RI, nullptr, X, nullptr,
        S_LEN, DIM, S_LEN, 1.0f,
        (long long)S_LEN * S_LEN, (long long)S_LEN * DIM, (long long)S_LEN * DIM);

    // 7) XO = X @ Wo^T + bo (NT, single-pass, fp32 out)
    mma_gemm_kernel<0,0><<<dim3(8, 128, 1), THREADS, SMEM_DYN>>>(
        X, W + 5*WSZ, bo, nullptr, XO, nullptr, nullptr,
        ROWS, DIM, DIM, 1.0f, 0, 0, 0);

    // 8) final dual LayerNorm
    ln_out_kernel<<<2 * ROWS, 128>>>(XO, ln_tg, ln_tb, ln_ig, ln_ib, out);
}

// round 12
// speedup vs baseline: 6.7657x; 1.0091x over previous
#include <cuda_runtime.h>
#include <cuda_fp16.h>
#include <cstdint>
#include <math.h>

// ============================================================================
// Problem constants
// ============================================================================
#define DIM   512
#define S_LEN 4096
#define NBAT  4
#define ROWS  (NBAT * S_LEN)      // 16384

// GEMM tiling: BM=128, BN=64, BK=32, 256 threads (8 warps, 4x2 grid, 32x32 warp tile)
#define BM 128
#define BN 64
#define BK 32
#define THREADS 256
#define STAGES 4
// stage layout: A 8KB | B 4KB = 12KB
#define ST_A 0
#define ST_B 8192
#define STB  12288
#define SMEM_DYN (STAGES * STB)   // 49152

// ============================================================================
// PTX helpers (plain sm_103-legal: cp.async / ldmatrix / mma.sync only)
// ============================================================================
__device__ __forceinline__ uint32_t smem_to_u32(const void* p) {
    uint32_t a;
    asm("{ .reg .u64 t; cvta.to.shared.u64 t, %1; cvt.u32.u64 %0, t; }" : "=r"(a) : "l"(p));
    return a;
}
#define CP_A16(s, g) \
    asm volatile("cp.async.cg.shared.global [%0], [%1], 16;" :: "r"(s), "l"(g))
#define CP_COMMIT() asm volatile("cp.async.commit_group;" ::: "memory")
#define CP_WAIT(n)  asm volatile("cp.async.wait_group %0;" :: "n"(n) : "memory")

__device__ __forceinline__ void ldm_x4(uint32_t* r, uint32_t addr) {
    asm volatile("ldmatrix.sync.aligned.m8n8.x4.shared.b16 {%0,%1,%2,%3}, [%4];"
        : "=r"(r[0]), "=r"(r[1]), "=r"(r[2]), "=r"(r[3]) : "r"(addr));
}
__device__ __forceinline__ void ldm_x4_t(uint32_t* r, uint32_t addr) {
    asm volatile("ldmatrix.sync.aligned.m8n8.x4.trans.shared.b16 {%0,%1,%2,%3}, [%4];"
        : "=r"(r[0]), "=r"(r[1]), "=r"(r[2]), "=r"(r[3]) : "r"(addr));
}
__device__ __forceinline__ void mma_f16(float* d, const uint32_t* a, const uint32_t* b) {
    asm volatile("mma.sync.aligned.m16n8k16.row.col.f32.f16.f16.f32 "
        "{%0,%1,%2,%3}, {%4,%5,%6,%7}, {%8,%9}, {%0,%1,%2,%3};"
        : "+f"(d[0]), "+f"(d[1]), "+f"(d[2]), "+f"(d[3])
        : "r"(a[0]), "r"(a[1]), "r"(a[2]), "r"(a[3]), "r"(b[0]), "r"(b[1]));
}

// ============================================================================
// Scratch buffers
// ============================================================================
__device__ __align__(128) __half g_norms[(size_t)ROWS * DIM];
__device__ __align__(128) __half g_Q[(size_t)ROWS * DIM];
__device__ __align__(128) __half g_K[(size_t)ROWS * DIM];
__device__ __align__(128) __half g_V[(size_t)ROWS * DIM];
__device__ __align__(128) __half g_E[(size_t)NBAT * S_LEN * S_LEN];   // exp(scores), fp16
__device__ __align__(128) __half g_X[(size_t)ROWS * DIM];
__device__ __align__(128) __half g_W[(size_t)6 * DIM * DIM];
__device__ __align__(128) float g_XO[(size_t)ROWS * DIM];

// ============================================================================
// Input LayerNorm -> fp16 norms
// ============================================================================
__global__ void __launch_bounds__(128) ln_in_kernel(
    const float* __restrict__ text, const float* __restrict__ img,
    const float* __restrict__ gt, const float* __restrict__ bt,
    const float* __restrict__ gi, const float* __restrict__ bi,
    __half* __restrict__ outH)
{
    int row = blockIdx.x;
    const float *src, *g, *b;
    if (row < 2 * S_LEN) { src = text + (size_t)row * DIM;              g = gt; b = bt; }
    else                 { src = img  + (size_t)(row - 2*S_LEN) * DIM;  g = gi; b = bi; }

    int t = threadIdx.x;
    float4 x = ((const float4*)src)[t];
    float s  = x.x + x.y + x.z + x.w;
    float ss = x.x*x.x + x.y*x.y + x.z*x.z + x.w*x.w;

    __shared__ float rs[4], rss[4];
    #pragma unroll
    for (int o = 16; o > 0; o >>= 1) {
        s  += __shfl_xor_sync(0xffffffffu, s,  o);
        ss += __shfl_xor_sync(0xffffffffu, ss, o);
    }
    if ((t & 31) == 0) { rs[t>>5] = s; rss[t>>5] = ss; }
    __syncthreads();
    s  = rs[0] + rs[1] + rs[2] + rs[3];
    ss = rss[0] + rss[1] + rss[2] + rss[3];

    float mu  = s * (1.0f / DIM);
    float var = ss * (1.0f / DIM) - mu * mu;
    float inv = rsqrtf(var + 1e-5f);

    float4 gg = ((const float4*)g)[t];
    float4 bb = ((const float4*)b)[t];
    float v0 = (x.x - mu) * inv * gg.x + bb.x;
    float v1 = (x.y - mu) * inv * gg.y + bb.y;
    float v2 = (x.z - mu) * inv * gg.z + bb.z;
    float v3 = (x.w - mu) * inv * gg.w + bb.w;

    size_t base = (size_t)row * DIM + t * 4;
    ((__half2*)(outH + base))[0] = __halves2half2(__float2half(v0), __float2half(v1));
    ((__half2*)(outH + base))[1] = __halves2half2(__float2half(v2), __float2half(v3));
}

// ============================================================================
// Convert 6 weight matrices to fp16
// ============================================================================
__global__ void __launch_bounds__(256) convert_weights_kernel(
    const float* __restrict__ w0, const float* __restrict__ w1,
    const float* __restrict__ w2, const float* __restrict__ w3,
    const float* __restrict__ w4, const float* __restrict__ w5,
    __half* __restrict__ W)
{
    int mat = blockIdx.y;
    const float* ws[6] = {w0, w1, w2, w3, w4, w5};
    const float* w = ws[mat];
    int i = blockIdx.x * 256 + threadIdx.x;
    W[(size_t)mat * DIM * DIM + i] = __float2half(w[i]);
}

// ============================================================================
// Final dual LayerNorm: one block per XO row, writes BOTH ln_t and ln_i rows
// ============================================================================
__global__ void __launch_bounds__(128) ln_out_dual_kernel(
    const float* __restrict__ x,
    const float* __restrict__ gt, const float* __restrict__ bt,
    const float* __restrict__ gi, const float* __restrict__ bi,
    float* __restrict__ out)
{
    int row = blockIdx.x;
    const float* src = x + (size_t)row * DIM;

    int t = threadIdx.x;
    float4 v = ((const float4*)src)[t];
    float s  = v.x + v.y + v.z + v.w;
    float ss = v.x*v.x + v.y*v.y + v.z*v.z + v.w*v.w;

    __shared__ float rs[4], rss[4];
    #pragma unroll
    for (int o = 16; o > 0; o >>= 1) {
        s  += __shfl_xor_sync(0xffffffffu, s,  o);
        ss += __shfl_xor_sync(0xffffffffu, ss, o);
    }
    if ((t & 31) == 0) { rs[t>>5] = s; rss[t>>5] = ss; }
    __syncthreads();
    s  = rs[0] + rs[1] + rs[2] + rs[3];
    ss = rss[0] + rss[1] + rss[2] + rss[3];

    float mu  = s * (1.0f / DIM);
    float var = ss * (1.0f / DIM) - mu * mu;
    float inv = rsqrtf(var + 1e-5f);

    float nx = (v.x - mu) * inv;
    float ny = (v.y - mu) * inv;
    float nz = (v.z - mu) * inv;
    float nw = (v.w - mu) * inv;

    float4 g1 = ((const float4*)gt)[t];
    float4 b1 = ((const float4*)bt)[t];
    float4 o1;
    o1.x = nx * g1.x + b1.x; o1.y = ny * g1.y + b1.y;
    o1.z = nz * g1.z + b1.z; o1.w = nw * g1.w + b1.w;
    ((float4*)(out + (size_t)row * DIM))[t] = o1;

    float4 g2 = ((const float4*)gi)[t];
    float4 b2 = ((const float4*)bi)[t];
    float4 o2;
    o2.x = nx * g2.x + b2.x; o2.y = ny * g2.y + b2.y;
    o2.z = nz * g2.z + b2.z; o2.w = nw * g2.w + b2.w;
    ((float4*)(out + ((size_t)(row + ROWS)) * DIM))[t] = o2;
}

// ============================================================================
// Shared GEMM core: mma.sync fp16 single-pass (BM=128, BN=64, BK=32, 256 thr)
// LAYOUT 0 (NT): B = [N,K] k-contiguous
// LAYOUT 1 (NN): B = [K,N] n-contiguous (ldmatrix.trans)
// EPI 0: fp32 C (alpha + bias)                      [Wo -> XO]
// EPI 1: fp16 C (alpha + bias)                      [projections]
// EPI 2: fp16 C = exp(min(alpha*acc,11))            [scores -> E]
// EPI 3: fp16 C = acc / rowsum(A)   (self-normalizing PV; rowsum from smem A)
// ============================================================================
template<int LAYOUT, int EPI>
__device__ __forceinline__ void gemm_core(
    const __half* __restrict__ A, const __half* __restrict__ B,
    const float* __restrict__ bias,
    float* __restrict__ Cf, __half* __restrict__ CH,
    int N, int K, float alpha, int m0, int n0, char* smemc)
{
    uint32_t base = smem_to_u32(smemc);
    int tid = threadIdx.x, wid = tid >> 5, lane = tid & 31;
    int NK = K / BK;

    auto load_stage = [&](int kt) {
        uint32_t sb = base + (uint32_t)(kt & (STAGES - 1)) * STB;
        int kb = kt * BK;
        #pragma unroll
        for (int i = 0; i < 2; i++) {
            int slot = tid + i * THREADS;
            int row = slot >> 2, unit = slot & 3;
            uint32_t off = (uint32_t)(row * 64 + unit * 16);
            off ^= (off >> 3) & 0x30;
            CP_A16(sb + ST_A + off, A + (size_t)(m0 + row) * K + kb + unit * 8);
        }
        if (LAYOUT == 0) {
            int row = tid >> 2, unit = tid & 3;
            uint32_t off = (uint32_t)(row * 64 + unit * 16);
            off ^= (off >> 3) & 0x30;
            CP_A16(sb + ST_B + off, B + (size_t)(n0 + row) * K + kb + unit * 8);
        } else {
            int row = tid >> 3, unit = tid & 7;
            uint32_t off = (uint32_t)(row * 128 + unit * 16);
            off ^= (off >> 3) & 0x70;
            CP_A16(sb + ST_B + off, B + (size_t)(kb + row) * N + n0 + unit * 8);
        }
    };

    load_stage(0); CP_COMMIT();
    load_stage(1); CP_COMMIT();
    load_stage(2); CP_COMMIT();

    int wm = wid & 3, wn = wid >> 2;     // 4x2 warp grid, 32x32 warp tile
    float acc[2][4][4];
    #pragma unroll
    for (int a = 0; a < 2; a++)
        #pragma unroll
        for (int b = 0; b < 4; b++)
            #pragma unroll
            for (int c = 0; c < 4; c++) acc[a][b][c] = 0.0f;

    float psum = 0.0f;   // EPI 3: partial row sum of A (this thread's slice)

    for (int kt = 0; kt < NK; kt++) {
        if (kt + 3 < NK)      { load_stage(kt + 3); CP_COMMIT(); CP_WAIT(3); }
        else if (kt + 2 < NK) { CP_WAIT(2); }
        else if (kt + 1 < NK) { CP_WAIT(1); }
        else                  { CP_WAIT(0); }
        __syncthreads();

        uint32_t sb = base + (uint32_t)(kt & (STAGES - 1)) * STB;

        #pragma unroll
        for (int ks = 0; ks < 2; ks++) {
            int k0 = ks * 16;

            uint32_t ar[2][4];
            #pragma unroll
            for (int mt = 0; mt < 2; mt++) {
                int row = wm * 32 + mt * 16 + (lane & 15);
                uint32_t off = (uint32_t)(row * 64 + k0 * 2 + ((lane >> 4) << 4));
                off ^= (off >> 3) & 0x30;
                ldm_x4(ar[mt], sb + ST_A + off);
            }

            uint32_t br[4][2];
            if (LAYOUT == 0) {
                #pragma unroll
                for (int p = 0; p < 2; p++) {
                    int nrow = wn * 32 + p * 16 + (lane & 7) + 8 * ((lane >> 4) & 1);
                    uint32_t off = (uint32_t)(nrow * 64 + k0 * 2 + ((lane >> 3) & 1) * 16);
                    off ^= (off >> 3) & 0x30;
                    uint32_t r[4];
                    ldm_x4(r, sb + ST_B + off);
                    br[p*2][0] = r[0]; br[p*2][1] = r[1];
                    br[p*2+1][0] = r[2]; br[p*2+1][1] = r[3];
                }
            } else {
                #pragma unroll
                for (int p = 0; p < 2; p++) {
                    int krow = k0 + (lane & 7) + 8 * ((lane >> 3) & 1);
                    int ncol = wn * 32 + p * 16 + 8 * (lane >> 4);
                    uint32_t off = (uint32_t)(krow * 128 + ncol * 2);
                    off ^= (off >> 3) & 0x70;
                    uint32_t r[4];
                    ldm_x4_t(r, sb + ST_B + off);
                    br[p*2][0] = r[0]; br[p*2][1] = r[1];
                    br[p*2+1][0] = r[2]; br[p*2+1][1] = r[3];
                }
            }

            #pragma unroll
            for (int mt = 0; mt < 2; mt++)
                #pragma unroll
                for (int nt = 0; nt < 4; nt++)
                    mma_f16(acc[mt][nt], ar[mt], br[nt]);
        }

        if (EPI == 3) {
            // Accumulate row sums of the A tile (thread pair per row: 2x16B each).
            uint32_t sboff = (uint32_t)(kt & (STAGES - 1)) * STB + ST_A;
            int row = tid >> 1;
            #pragma unroll
            for (int u = 0; u < 2; u++) {
                uint32_t off = (uint32_t)(row * 64 + ((tid & 1) * 2 + u) * 16);
                off ^= (off >> 3) & 0x30;
                uint4 v = *(const uint4*)(smemc + sboff + off);
                const __half2* h = (const __half2*)&v;
                #pragma unroll
                for (int j = 0; j < 4; j++) {
                    float2 f = __half22float2(h[j]);
                    psum += f.x + f.y;
                }
            }
        }
        __syncthreads();
    }

    // ---------------- epilogue ----------------
    float* rowsumSm = (float*)smemc;   // EPI 3 only; pipeline smem is free now
    if (EPI == 3) {
        psum += __shfl_xor_sync(0xffffffffu, psum, 1);
        if ((tid & 1) == 0) rowsumSm[tid >> 1] = psum;
        __syncthreads();
    }

    #pragma unroll
    for (int mt = 0; mt < 2; mt++) {
        int lr   = wm * 32 + mt * 16 + (lane >> 2);   // local row in [0,128)
        int mrow = m0 + lr;
        float rs0 = 1.0f, rs1 = 1.0f;
        if (EPI == 3) {
            rs0 = 1.0f / rowsumSm[lr];
            rs1 = 1.0f / rowsumSm[lr + 8];
        }
        #pragma unroll
        for (int nt = 0; nt < 4; nt++) {
            int n = n0 + wn * 32 + nt * 8 + (lane & 3) * 2;
            float c0, c1, c2, c3;
            if (EPI == 0 || EPI == 1) {
                float b0 = bias ? __ldg(&bias[n])     : 0.0f;
                float b1 = bias ? __ldg(&bias[n + 1]) : 0.0f;
                c0 = alpha * acc[mt][nt][0] + b0;
                c1 = alpha * acc[mt][nt][1] + b1;
                c2 = alpha * acc[mt][nt][2] + b0;
                c3 = alpha * acc[mt][nt][3] + b1;
            } else if (EPI == 2) {
                c0 = __expf(fminf(alpha * acc[mt][nt][0], 11.0f));
                c1 = __expf(fminf(alpha * acc[mt][nt][1], 11.0f));
                c2 = __expf(fminf(alpha * acc[mt][nt][2], 11.0f));
                c3 = __expf(fminf(alpha * acc[mt][nt][3], 11.0f));
            } else {  // EPI == 3
                c0 = acc[mt][nt][0] * rs0;
                c1 = acc[mt][nt][1] * rs0;
                c2 = acc[mt][nt][2] * rs1;
                c3 = acc[mt][nt][3] * rs1;
            }
            size_t o0 = (size_t)mrow * N + n;
            size_t o1 = (size_t)(mrow + 8) * N + n;
            if (EPI == 0) {
                *(float2*)(Cf + o0) = make_float2(c0, c1);
                *(float2*)(Cf + o1) = make_float2(c2, c3);
            } else {
                *(__half2*)(CH + o0) = __halves2half2(__float2half(c0), __float2half(c1));
                *(__half2*)(CH + o1) = __halves2half2(__float2half(c2), __float2half(c3));
            }
        }
    }
}

// Generic batched wrapper
template<int LAYOUT, int EPI>
__global__ void __launch_bounds__(THREADS, 2) mma_gemm_kernel(
    const __half* __restrict__ A, const __half* __restrict__ B,
    const float* __restrict__ bias,
    float* __restrict__ Cf, __half* __restrict__ CH,
    int N, int K, float alpha,
    long long sA, long long sB, long long sC)
{
    extern __shared__ char smem[];
    int z = blockIdx.z;
    gemm_core<LAYOUT, EPI>(
        A + (size_t)z * sA, B + (size_t)z * sB, bias,
        Cf ? Cf + (size_t)z * sC : nullptr,
        CH ? CH + (size_t)z * sC : nullptr,
        N, K, alpha, blockIdx.y * BM, blockIdx.x * BN, smem);
}

// Merged projection kernel: Q, Kt, Ki, Vt, Vi in one launch.
// grid = (8, 384): y<128 Q | y<192 Kt | y<256 Ki | y<320 Vt | y<384 Vi
__global__ void __launch_bounds__(THREADS, 2) proj_kernel(
    const __half* __restrict__ NORM, const __half* __restrict__ W,
    const float* __restrict__ bq, const float* __restrict__ bkt,
    const float* __restrict__ bki, const float* __restrict__ bvt,
    const float* __restrict__ bvi,
    __half* __restrict__ Q, __half* __restrict__ K, __half* __restrict__ V)
{
    extern __shared__ char smem[];
    const size_t WSZ = (size_t)DIM * DIM;
    int y = blockIdx.y;
    int mat, arow;
    __half* outp;
    const float* bias;
    if (y < 128)      { mat = 0; arow = y * 128;                outp = Q; bias = bq; }
    else if (y < 192) { mat = 1; arow = (y - 128) * 128;        outp = K; bias = bkt; }
    else if (y < 256) { mat = 3; arow = 8192 + (y - 192) * 128; outp = K; bias = bki; }
    else if (y < 320) { mat = 2; arow = (y - 256) * 128;        outp = V; bias = bvt; }
    else              { mat = 4; arow = 8192 + (y - 320) * 128; outp = V; bias = bvi; }

    gemm_core<0, 1>(
        NORM + (size_t)arow * DIM, W + (size_t)mat * WSZ, bias,
        nullptr, outp + (size_t)arow * DIM,
        DIM, DIM, 1.0f, 0, blockIdx.x * BN, smem);
}

// ============================================================================
// Host orchestration
// ============================================================================
extern "C" void kernel_launch(void* const* d_in, const int* in_sizes, int n_in,
                              void* d_out, int out_size)
{
    const float* text  = (const float*)d_in[0];
    const float* img   = (const float*)d_in[1];
    const float* ln_tg = (const float*)d_in[2];
    const float* ln_tb = (const float*)d_in[3];
    const float* ln_ig = (const float*)d_in[4];
    const float* ln_ib = (const float*)d_in[5];
    const float* Wq  = (const float*)d_in[6];  const float* bq  = (const float*)d_in[7];
    const float* Wkt = (const float*)d_in[8];  const float* bkt = (const float*)d_in[9];
    const float* Wvt = (const float*)d_in[10]; const float* bvt = (const float*)d_in[11];
    const float* Wki = (const float*)d_in[12]; const float* bki = (const float*)d_in[13];
    const float* Wvi = (const float*)d_in[14]; const float* bvi = (const float*)d_in[15];
    const float* Wo  = (const float*)d_in[16]; const float* bo  = (const float*)d_in[17];
    float* out = (float*)d_out;

    static bool attr_done = false;
    if (!attr_done) {
        cudaFuncSetAttribute(proj_kernel,          cudaFuncAttributeMaxDynamicSharedMemorySize, SMEM_DYN);
        cudaFuncSetAttribute(mma_gemm_kernel<0,0>, cudaFuncAttributeMaxDynamicSharedMemorySize, SMEM_DYN);
        cudaFuncSetAttribute(mma_gemm_kernel<0,2>, cudaFuncAttributeMaxDynamicSharedMemorySize, SMEM_DYN);
        cudaFuncSetAttribute(mma_gemm_kernel<1,3>, cudaFuncAttributeMaxDynamicSharedMemorySize, SMEM_DYN);
        attr_done = true;
    }

    void *pN, *pQ, *pK, *pV, *pE, *pX, *pW, *pXO;
    cudaGetSymbolAddress(&pN, g_norms);
    cudaGetSymbolAddress(&pQ, g_Q); cudaGetSymbolAddress(&pK, g_K); cudaGetSymbolAddress(&pV, g_V);
    cudaGetSymbolAddress(&pE, g_E); cudaGetSymbolAddress(&pX, g_X);
    cudaGetSymbolAddress(&pW, g_W); cudaGetSymbolAddress(&pXO, g_XO);

    __half* NORM = (__half*)pN;
    __half* Q = (__half*)pQ; __half* K = (__half*)pK; __half* V = (__half*)pV;
    __half* E = (__half*)pE; __half* X = (__half*)pX;
    __half* W = (__half*)pW;
    float* XO = (float*)pXO;

    const float scale = 0.04419417382415922f;  // 512^-0.5
    const size_t WSZ = (size_t)DIM * DIM;      // 262144

    // 1) input LN -> fp16 norms
    ln_in_kernel<<<ROWS, 128>>>(text, img, ln_tg, ln_tb, ln_ig, ln_ib, NORM);

    // 2) convert weights (order: q, kt, vt, ki, vi, o)
    convert_weights_kernel<<<dim3(1024, 6), 256>>>(Wq, Wkt, Wvt, Wki, Wvi, Wo, W);

    // 3) all projections, one launch
    proj_kernel<<<dim3(8, 384), THREADS, SMEM_DYN>>>(
        NORM, W, bq, bkt, bki, bvt, bvi, Q, K, V);

    // 4) E = exp(scale * Q @ K^T) (batched NT)
    mma_gemm_kernel<0,2><<<dim3(64, 32, NBAT), THREADS, SMEM_DYN>>>(
        Q, K, nullptr, nullptr, E,
        S_LEN, DIM, scale,
        (long long)S_LEN * DIM, (long long)S_LEN * DIM, (long long)S_LEN * S_LEN);

    // 5) X = (E @ V) / rowsum(E) (batched NN, self-normalizing)
    mma_gemm_kernel<1,3><<<dim3(8, 32, NBAT), THREADS, SMEM_DYN>>>(
        E, V, nullptr, nullptr, X,
        DIM, S_LEN, 1.0f,
        (long long)S_LEN * S_LEN, (long long)S_LEN * DIM, (long long)S_LEN * DIM);

    // 6) XO = X @ Wo^T + bo (NT, fp32 out)
    mma_gemm_kernel<0,0><<<dim3(8, 128, 1), THREADS, SMEM_DYN>>>(
        X, W + 5*WSZ, bo, XO, nullptr,
        DIM, DIM, 1.0f, 0, 0, 0);

    // 7) final dual LayerNorm (one block per XO row, both outputs)
    ln_out_dual_kernel<<<ROWS, 128>>>(XO, ln_tg, ln_tb, ln_ig, ln_ib, out);
}